// round 8
// baseline (speedup 1.0000x reference)
#include <cuda_runtime.h>
#include <cuda_bf16.h>
#include <cstdint>

#define B_  4
#define NXq 1024
#define NYk 1024
#define C_  768
#define H_  12
#define D_  64

// ======================= scratch (static device globals) =======================
__device__ __align__(16) __nv_bfloat16 g_x16 [B_*NXq*C_];
__device__ __align__(16) __nv_bfloat16 g_yn16[B_*NYk*C_];
__device__ __align__(16) __nv_bfloat16 g_q16 [B_*NXq*C_];
__device__ __align__(16) __nv_bfloat16 g_kv16[B_*NYk*2*C_];
__device__ __align__(16) __nv_bfloat16 g_vt16[48*64*1024];
__device__ __align__(16) __nv_bfloat16 g_W   [48u*1024u*1024u];
__device__ __align__(16) __nv_bfloat16 g_at16[B_*NXq*C_];
__device__ __align__(16) __nv_bfloat16 g_qw16 [C_*C_];
__device__ __align__(16) __nv_bfloat16 g_kvw16[2*C_*C_];
__device__ __align__(16) __nv_bfloat16 g_pw16 [C_*C_];

__device__ __forceinline__ uint32_t smem_u32(const void* p) {
    uint32_t a;
    asm("{ .reg .u64 t; cvta.to.shared.u64 t, %1; cvt.u32.u64 %0, t; }" : "=r"(a) : "l"(p));
    return a;
}
__device__ __forceinline__ void cp16(uint32_t dst, const void* src) {
    asm volatile("cp.async.cg.shared.global [%0], [%1], 16;" :: "r"(dst), "l"(src));
}

// ======================= fused multiscale conv + LayerNorm -> bf16 =======================
__global__ void __launch_bounds__(256) conv_ln_kernel(
    const float* __restrict__ y,
    const float* __restrict__ c1w, const float* __restrict__ c1b,
    const float* __restrict__ c2w, const float* __restrict__ c2b,
    const float* __restrict__ c3w, const float* __restrict__ c3b,
    const float* __restrict__ lnw, const float* __restrict__ lnb)
{
    int row = blockIdx.x;
    int b  = row >> 10;
    int ny = row & 1023;
    const float* yb = y + (size_t)b * NYk * C_;
    int tid = threadIdx.x;

    float vals[3];
    float lsum = 0.f, lsq = 0.f;
    #pragma unroll
    for (int i = 0; i < 3; i++) {
        int c = tid + i * 256;
        float w7[7];
        #pragma unroll
        for (int j = 0; j < 7; j++) w7[j] = c3w[c*7 + j];
        #pragma unroll
        for (int j = 0; j < 5; j++) w7[j+1] += c2w[c*5 + j];
        #pragma unroll
        for (int j = 0; j < 3; j++) w7[j+2] += c1w[c*3 + j];
        float acc = c1b[c] + c2b[c] + c3b[c];
        #pragma unroll
        for (int j = 0; j < 7; j++) {
            int nn = ny + j - 3;
            if (nn >= 0 && nn < NYk) acc += w7[j] * yb[(size_t)nn * C_ + c];
        }
        vals[i] = acc; lsum += acc; lsq += acc * acc;
    }

    __shared__ float s1[256], s2[256];
    s1[tid] = lsum; s2[tid] = lsq;
    __syncthreads();
    for (int s = 128; s > 0; s >>= 1) {
        if (tid < s) { s1[tid] += s1[tid+s]; s2[tid] += s2[tid+s]; }
        __syncthreads();
    }
    float mean = s1[0] * (1.0f / C_);
    float var  = s2[0] * (1.0f / C_) - mean * mean;
    float rstd = rsqrtf(var + 1e-5f);

    size_t base = (size_t)row * C_;
    #pragma unroll
    for (int i = 0; i < 3; i++) {
        int c = tid + i * 256;
        float v = (vals[i] - mean) * rstd * lnw[c] + lnb[c];
        g_yn16[base + c] = __float2bfloat16(v);
    }
}

// ======================= fp32 -> bf16 convert =======================
__global__ void __launch_bounds__(256) cvt_kernel(const float* __restrict__ s,
                                                  __nv_bfloat16* __restrict__ o,
                                                  int n4)
{
    int i = blockIdx.x * 256 + threadIdx.x;
    if (i >= n4) return;
    float4 v = ((const float4*)s)[i];
    __nv_bfloat162* O = (__nv_bfloat162*)o;
    O[2*i]   = __halves2bfloat162(__float2bfloat16(v.x), __float2bfloat16(v.y));
    O[2*i+1] = __halves2bfloat162(__float2bfloat16(v.z), __float2bfloat16(v.w));
}

// ======================= V transpose =======================
__global__ void __launch_bounds__(256) vtrans_kernel()
{
    int z  = blockIdx.x;
    int t0 = blockIdx.y * 32;
    int b = z / 12, h = z - b*12;
    __shared__ __nv_bfloat16 sh[64][33];
    int tid = threadIdx.x;
    #pragma unroll
    for (int i = 0; i < 8; i++) {
        int idx = tid + i*256;
        int tok = idx >> 6, d = idx & 63;
        size_t off = ((size_t)(b*1024 + t0 + tok)) * 1536 + 768 + h*64 + d;
        sh[d][tok] = g_kv16[off];
    }
    __syncthreads();
    #pragma unroll
    for (int i = 0; i < 8; i++) {
        int o = tid + i*256;
        int d = o >> 5, c = o & 31;
        size_t off = (size_t)z * 64 * 1024 + (size_t)d * 1024 + t0 + c;
        g_vt16[off] = sh[d][c];
    }
}

// ======================= HMMA GEMM (R5, proven) =======================
template<int NT, int OUTM>
__global__ void __launch_bounds__(256) mma_gemm(
    const __nv_bfloat16* __restrict__ A, const __nv_bfloat16* __restrict__ B,
    float* __restrict__ Co, __nv_bfloat16* __restrict__ Cb,
    const float* __restrict__ bias, const float* __restrict__ res,
    int K, int lda, int ldb, int ldc, float alpha, int HH,
    long long aO, long long aI, long long bO, long long bI,
    long long cO, long long cI)
{
    constexpr int WM  = (NT == 128) ? 2 : 4;
    constexpr int WN  = 8 / WM;
    constexpr int WTM = 128 / WM;
    constexpr int WTN = NT / WN;
    constexpr int MT  = WTM / 16;
    constexpr int NTT = WTN / 8;
    constexpr int PITCH = 72;
    constexpr int ABYTES = 128 * PITCH * 2;
    constexpr int BBYTES = NT  * PITCH * 2;
    constexpr int STAGE  = ABYTES + BBYTES;

    extern __shared__ __align__(16) char dsm[];
    uint32_t smbase = smem_u32(dsm);

    int tid = threadIdx.x, wid = tid >> 5, lane = tid & 31;
    int wm = wid % WM, wn = wid / WM;

    int z = blockIdx.z, zo = z / HH, zi = z - zo * HH;
    A += zo*aO + zi*aI;
    B += zo*bO + zi*bI;
    long long coff = zo*cO + zi*cI;

    long long m0 = (long long)blockIdx.y * 128;
    long long n0 = (long long)blockIdx.x * NT;

    float acc[MT][NTT][4];
    #pragma unroll
    for (int i = 0; i < MT; i++)
        #pragma unroll
        for (int j = 0; j < NTT; j++)
            #pragma unroll
            for (int r = 0; r < 4; r++) acc[i][j][r] = 0.f;

    int nIter = K >> 6;

    uint32_t a_off = ((uint32_t)(wm*WTM + (lane & 15)) * PITCH + ((lane >> 4) << 3)) * 2;
    uint32_t b_off = ABYTES + ((uint32_t)(wn*WTN + (lane & 7)) * PITCH + (((lane >> 3) & 1) << 3)) * 2;

    auto issue = [&](int t) {
        int k0 = t << 6, s = t & 1;
        uint32_t sa = smbase + s * STAGE;
        uint32_t sb = sa + ABYTES;
        #pragma unroll
        for (int i = 0; i < 4; i++) {
            int ch = tid + (i << 8);
            int r = ch >> 3, c = (ch & 7) << 3;
            cp16(sa + (uint32_t)(r*PITCH + c)*2, A + (m0 + r)*lda + k0 + c);
        }
        #pragma unroll
        for (int i = 0; i < NT/32; i++) {
            int ch = tid + (i << 8);
            int r = ch >> 3, c = (ch & 7) << 3;
            cp16(sb + (uint32_t)(r*PITCH + c)*2, B + (n0 + r)*ldb + k0 + c);
        }
        asm volatile("cp.async.commit_group;");
    };

    issue(0);
    for (int t = 0; t < nIter; t++) {
        if (t + 1 < nIter) {
            issue(t + 1);
            asm volatile("cp.async.wait_group 1;");
        } else {
            asm volatile("cp.async.wait_group 0;");
        }
        __syncthreads();
        uint32_t stg = smbase + (uint32_t)(t & 1) * STAGE;
        uint32_t abase = stg + a_off;
        uint32_t bbase = stg + b_off;

        #pragma unroll
        for (int ks = 0; ks < 4; ks++) {
            uint32_t kb = (uint32_t)ks << 5;
            uint32_t af[MT][4];
            #pragma unroll
            for (int mt = 0; mt < MT; mt++) {
                asm volatile("ldmatrix.sync.aligned.m8n8.x4.shared.b16 {%0,%1,%2,%3}, [%4];"
                    : "=r"(af[mt][0]), "=r"(af[mt][1]), "=r"(af[mt][2]), "=r"(af[mt][3])
                    : "r"(abase + (uint32_t)(mt*16*PITCH*2) + kb));
            }
            uint32_t bf[NTT][2];
            #pragma unroll
            for (int nt = 0; nt < NTT; nt++) {
                asm volatile("ldmatrix.sync.aligned.m8n8.x2.shared.b16 {%0,%1}, [%2];"
                    : "=r"(bf[nt][0]), "=r"(bf[nt][1])
                    : "r"(bbase + (uint32_t)(nt*8*PITCH*2) + kb));
            }
            #pragma unroll
            for (int mt = 0; mt < MT; mt++)
                #pragma unroll
                for (int nt = 0; nt < NTT; nt++) {
                    asm volatile(
                        "mma.sync.aligned.m16n8k16.row.col.f32.bf16.bf16.f32 "
                        "{%0,%1,%2,%3}, {%4,%5,%6,%7}, {%8,%9}, {%0,%1,%2,%3};"
                        : "+f"(acc[mt][nt][0]), "+f"(acc[mt][nt][1]),
                          "+f"(acc[mt][nt][2]), "+f"(acc[mt][nt][3])
                        : "r"(af[mt][0]), "r"(af[mt][1]), "r"(af[mt][2]), "r"(af[mt][3]),
                          "r"(bf[nt][0]), "r"(bf[nt][1]));
                }
        }
        __syncthreads();
    }

    int gg = lane >> 2, qq = lane & 3;
    #pragma unroll
    for (int mt = 0; mt < MT; mt++) {
        long long gm = m0 + wm*WTM + mt*16 + gg;
        #pragma unroll
        for (int nt = 0; nt < NTT; nt++) {
            long long gn = n0 + wn*WTN + nt*8 + 2*qq;
            float v0 = acc[mt][nt][0] * alpha;
            float v1 = acc[mt][nt][1] * alpha;
            float v2 = acc[mt][nt][2] * alpha;
            float v3 = acc[mt][nt][3] * alpha;
            long long gi0 = coff + gm * (long long)ldc + gn;
            long long gi1 = gi0 + 8LL * ldc;
            if (OUTM == 0) {
                *(float2*)&Co[gi0] = make_float2(v0, v1);
                *(float2*)&Co[gi1] = make_float2(v2, v3);
            } else if (OUTM == 1) {
                float b0 = bias[gn], b1 = bias[gn + 1];
                float2 r0 = *(const float2*)&res[gi0];
                float2 r1 = *(const float2*)&res[gi1];
                *(float2*)&Co[gi0] = make_float2(v0 + b0 + r0.x, v1 + b1 + r0.y);
                *(float2*)&Co[gi1] = make_float2(v2 + b0 + r1.x, v3 + b1 + r1.y);
            } else {
                *(__nv_bfloat162*)&Cb[gi0] =
                    __halves2bfloat162(__float2bfloat16(v0), __float2bfloat16(v1));
                *(__nv_bfloat162*)&Cb[gi1] =
                    __halves2bfloat162(__float2bfloat16(v2), __float2bfloat16(v3));
            }
        }
    }
}

// ======================= FUSED score GEMM + dual top-k + softmax weights =======================
// 32x1024 score tile kept in SHARED MEMORY as monotone u-keys (no S in HBM).
// Phase 1: HMMA scores, per-chunk 16-reg accumulators flushed to smem.
// Phase 2: warp-per-row radix select (R7 algorithm) reading keys from smem.
#define SP      1028                       // S smem row pitch (words)
#define A_OFF   0u                         // 32*72*2 = 4608 B
#define BC_OFF  4608u                      // 2 x 128*72*2 = 36864 B
#define BSTG    18432u
#define H_OFF   41472u                     // 8 x 512 x 4 = 16384 B
#define S_OFF   57856u                     // 32 x 1028 x 4 = 131584 B
#define SS_SMEM (57856 + 32*SP*4)          // 189440 B

__global__ void __launch_bounds__(256) score_select_kernel(
    const int* __restrict__ pk1, const int* __restrict__ pk2)
{
    extern __shared__ __align__(16) char dsm[];
    uint32_t smb = smem_u32(dsm);
    unsigned* sm_S = (unsigned*)(dsm + S_OFF);

    constexpr int PITCH = 72;

    int tid = threadIdx.x, w = tid >> 5, lane = tid & 31;
    int gg = lane >> 2, qq = lane & 3;
    int head = blockIdx.y;
    int b = head / 12, h = head - b*12;
    int m0 = blockIdx.x * 32;

    const __nv_bfloat16* Aq = g_q16  + (size_t)(b*1024 + m0) * 768 + h*64;
    const __nv_bfloat16* Kb = g_kv16 + (size_t)(b*1024) * 1536 + h*64;

    int k1 = *pk1, k2 = *pk2;

    auto issueB = [&](int c) {
        uint32_t sb = smb + BC_OFF + (uint32_t)(c & 1) * BSTG;
        const __nv_bfloat16* Bp = Kb + (size_t)(c * 128) * 1536;
        #pragma unroll
        for (int i = 0; i < 4; i++) {
            int ch = tid + (i << 8);
            int r = ch >> 3, col = (ch & 7) << 3;
            cp16(sb + (uint32_t)(r*PITCH + col)*2, Bp + (size_t)r*1536 + col);
        }
        asm volatile("cp.async.commit_group;");
    };

    {   // A tile (32x64), part of group 0
        int r = tid >> 3, col = (tid & 7) << 3;
        cp16(smb + A_OFF + (uint32_t)(r*PITCH + col)*2, Aq + (size_t)r*768 + col);
    }
    issueB(0);

    uint32_t a_off = A_OFF + ((uint32_t)(lane & 15) * PITCH + ((lane >> 4) << 3)) * 2;
    uint32_t b_off = ((uint32_t)((lane & 7) + w*16) * PITCH + (((lane >> 3) & 1) << 3)) * 2;

    // ---------------- phase 1: scores -> smem keys ----------------
    uint32_t af[2][4][4];
    #pragma unroll 1
    for (int c = 0; c < 8; c++) {
        if (c < 7) {
            issueB(c + 1);
            asm volatile("cp.async.wait_group 1;");
        } else {
            asm volatile("cp.async.wait_group 0;");
        }
        __syncthreads();
        if (c == 0) {
            #pragma unroll
            for (int mt = 0; mt < 2; mt++)
                #pragma unroll
                for (int ks = 0; ks < 4; ks++) {
                    asm volatile("ldmatrix.sync.aligned.m8n8.x4.shared.b16 {%0,%1,%2,%3}, [%4];"
                        : "=r"(af[mt][ks][0]), "=r"(af[mt][ks][1]),
                          "=r"(af[mt][ks][2]), "=r"(af[mt][ks][3])
                        : "r"(smb + a_off + (uint32_t)(mt*16*PITCH*2) + ((uint32_t)ks << 5)));
                }
        }
        float acc[2][2][4];
        #pragma unroll
        for (int mt = 0; mt < 2; mt++)
            #pragma unroll
            for (int nt = 0; nt < 2; nt++)
                #pragma unroll
                for (int e = 0; e < 4; e++) acc[mt][nt][e] = 0.f;

        uint32_t bb = smb + BC_OFF + (uint32_t)(c & 1) * BSTG + b_off;
        #pragma unroll
        for (int ks = 0; ks < 4; ks++) {
            uint32_t bf[2][2];
            #pragma unroll
            for (int nt = 0; nt < 2; nt++) {
                asm volatile("ldmatrix.sync.aligned.m8n8.x2.shared.b16 {%0,%1}, [%2];"
                    : "=r"(bf[nt][0]), "=r"(bf[nt][1])
                    : "r"(bb + (uint32_t)(nt*8*PITCH*2) + ((uint32_t)ks << 5)));
            }
            #pragma unroll
            for (int mt = 0; mt < 2; mt++)
                #pragma unroll
                for (int nt = 0; nt < 2; nt++) {
                    asm volatile(
                        "mma.sync.aligned.m16n8k16.row.col.f32.bf16.bf16.f32 "
                        "{%0,%1,%2,%3}, {%4,%5,%6,%7}, {%8,%9}, {%0,%1,%2,%3};"
                        : "+f"(acc[mt][nt][0]), "+f"(acc[mt][nt][1]),
                          "+f"(acc[mt][nt][2]), "+f"(acc[mt][nt][3])
                        : "r"(af[mt][ks][0]), "r"(af[mt][ks][1]),
                          "r"(af[mt][ks][2]), "r"(af[mt][ks][3]),
                          "r"(bf[nt][0]), "r"(bf[nt][1]));
                }
        }
        // flush chunk to smem keys
        #pragma unroll
        for (int mt = 0; mt < 2; mt++)
            #pragma unroll
            for (int nt = 0; nt < 2; nt++)
                #pragma unroll
                for (int pr = 0; pr < 2; pr++) {
                    int row = gg + 8*pr + 16*mt;
                    int col = c*128 + w*16 + nt*8 + 2*qq;
                    uint2 kk;
                    float v0 = acc[mt][nt][2*pr]     * 0.125f;
                    float v1 = acc[mt][nt][2*pr + 1] * 0.125f;
                    unsigned b0 = __float_as_uint(v0);
                    unsigned b1 = __float_as_uint(v1);
                    kk.x = (b0 & 0x80000000u) ? ~b0 : (b0 | 0x80000000u);
                    kk.y = (b1 & 0x80000000u) ? ~b1 : (b1 | 0x80000000u);
                    *(uint2*)&sm_S[row*SP + col] = kk;
                }
        __syncthreads();
    }

    // ---------------- phase 2: warp-per-row select ----------------
    unsigned* h0 = (unsigned*)(dsm + H_OFF) + w * 512;
    unsigned* h1 = h0 + 256;

    auto scan1 = [&](const unsigned* hh, unsigned pfx, int kk, int sh,
                     unsigned& pout, int& kout) {
        unsigned h8[8];
        #pragma unroll
        for (int i = 0; i < 8; i++) h8[i] = hh[lane*8 + i];
        unsigned tot = 0;
        #pragma unroll
        for (int i = 0; i < 8; i++) tot += h8[i];
        unsigned s = tot;
        #pragma unroll
        for (int d = 1; d < 32; d <<= 1) {
            unsigned t = __shfl_down_sync(0xFFFFFFFFu, s, d);
            if (lane + d < 32) s += t;
        }
        unsigned run = s - tot;
        unsigned myp = 0u; int myk = 0; bool found = false;
        #pragma unroll
        for (int i = 7; i >= 0; i--) {
            unsigned cn = run;
            run += h8[i];
            if (!found && run >= (unsigned)kk && cn < (unsigned)kk) {
                found = true;
                myp = pfx | ((unsigned)(lane*8 + i) << sh);
                myk = kk - (int)cn;
            }
        }
        unsigned ball = __ballot_sync(0xFFFFFFFFu, found);
        int src = __ffs(ball) - 1;
        pout = __shfl_sync(0xFFFFFFFFu, myp, src);
        kout = __shfl_sync(0xFFFFFFFFu, myk, src);
    };

    #pragma unroll 1
    for (int rr = 0; rr < 4; rr++) {
        int row = rr * 8 + w;
        const unsigned* Sr = sm_S + row * SP;

        unsigned u[32];
        unsigned umax = 0u;
        #pragma unroll
        for (int j = 0; j < 8; j++) {
            uint4 q4 = *(const uint4*)&Sr[j*128 + lane*4];
            u[j*4+0] = q4.x; u[j*4+1] = q4.y; u[j*4+2] = q4.z; u[j*4+3] = q4.w;
            umax = (q4.x > umax) ? q4.x : umax;
            umax = (q4.y > umax) ? q4.y : umax;
            umax = (q4.z > umax) ? q4.z : umax;
            umax = (q4.w > umax) ? q4.w : umax;
        }
        #pragma unroll
        for (int d = 16; d > 0; d >>= 1) {
            unsigned o = __shfl_xor_sync(0xFFFFFFFFu, umax, d);
            umax = (o > umax) ? o : umax;
        }
        float m = (umax & 0x80000000u) ? __uint_as_float(umax & 0x7FFFFFFFu)
                                       : __uint_as_float(~umax);

        // level 3
        #pragma unroll
        for (int i = 0; i < 8; i++) h0[lane*8 + i] = 0u;
        __syncwarp();
        #pragma unroll
        for (int j = 0; j < 32; j++) atomicAdd(&h0[u[j] >> 24], 1u);
        __syncwarp();
        unsigned p1, p2; int kk1, kk2;
        scan1(h0, 0u, k1, 24, p1, kk1);
        scan1(h0, 0u, k2, 24, p2, kk2);

        // levels 2..0
        #pragma unroll
        for (int lev = 2; lev >= 0; lev--) {
            int sh = lev * 8;
            unsigned himask = 0xFFFFFFFFu << (sh + 8);
            bool same = (p1 == p2);
            __syncwarp();
            #pragma unroll
            for (int i = 0; i < 16; i++) h0[lane*16 + i] = 0u;
            __syncwarp();
            #pragma unroll
            for (int j = 0; j < 32; j++) {
                unsigned uu = u[j];
                if (((uu ^ p1) & himask) == 0u) atomicAdd(&h0[(uu >> sh) & 255u], 1u);
                if (!same && ((uu ^ p2) & himask) == 0u) atomicAdd(&h1[(uu >> sh) & 255u], 1u);
            }
            __syncwarp();
            unsigned p1o = p1, p2o = p2;
            scan1(h0, p1o, kk1, sh, p1, kk1);
            scan1(same ? h0 : h1, p2o, kk2, sh, p2, kk2);
        }

        // Z sums with cached exponentials
        float ev[32];
        float z1 = 0.f, z2 = 0.f;
        #pragma unroll
        for (int j = 0; j < 32; j++) {
            unsigned uu = u[j];
            float v = (uu & 0x80000000u) ? __uint_as_float(uu & 0x7FFFFFFFu)
                                         : __uint_as_float(~uu);
            float e = __expf(v - m);
            ev[j] = e;
            if (uu >= p1) z1 += e;
            if (uu >= p2) z2 += e;
        }
        #pragma unroll
        for (int d = 16; d > 0; d >>= 1) {
            z1 += __shfl_xor_sync(0xFFFFFFFFu, z1, d);
            z2 += __shfl_xor_sync(0xFFFFFFFFu, z2, d);
        }
        float c1 = 0.6f / z1;
        float c2 = 0.4f / z2;

        __nv_bfloat16* Wrow = g_W + (size_t)head * 1024 * 1024 + (size_t)(m0 + row) * 1024;
        #pragma unroll
        for (int j = 0; j < 8; j++) {
            __nv_bfloat16 o4[4];
            #pragma unroll
            for (int e = 0; e < 4; e++) {
                unsigned uu = u[j*4 + e];
                float x = ev[j*4 + e];
                float wv = x * ((uu >= p1) ? c1 : 0.f) + x * ((uu >= p2) ? c2 : 0.f);
                o4[e] = __float2bfloat16(wv);
            }
            *(uint2*)&Wrow[j*128 + lane*4] = *(uint2*)o4;
        }
    }
}

// ======================= launch =======================
extern "C" void kernel_launch(void* const* d_in, const int* in_sizes, int n_in,
                              void* d_out, int out_size)
{
    const float* x   = (const float*)d_in[0];
    const float* y   = (const float*)d_in[1];
    const float* c1w = (const float*)d_in[2];
    const float* c1b = (const float*)d_in[3];
    const float* c2w = (const float*)d_in[4];
    const float* c2b = (const float*)d_in[5];
    const float* c3w = (const float*)d_in[6];
    const float* c3b = (const float*)d_in[7];
    const float* lnw = (const float*)d_in[8];
    const float* lnb = (const float*)d_in[9];
    const float* qw  = (const float*)d_in[10];
    const float* kvw = (const float*)d_in[11];
    const float* pw  = (const float*)d_in[12];
    const float* pb  = (const float*)d_in[13];
    const int*   pk1 = (const int*)d_in[14];
    const int*   pk2 = (const int*)d_in[15];
    float* out = (float*)d_out;

    #define SYM(p, g) void* p; cudaGetSymbolAddress(&p, g)
    SYM(x16, g_x16);   SYM(yn16, g_yn16);
    SYM(q16, g_q16);   SYM(kv16, g_kv16);
    SYM(vt16, g_vt16); SYM(W, g_W);
    SYM(at16, g_at16);
    SYM(qw16, g_qw16); SYM(kvw16, g_kvw16); SYM(pw16, g_pw16);
    #undef SYM

    const int SM128 = 2 * (128 + 128) * 72 * 2;   // 73728
    const int SM64  = 2 * (128 + 64)  * 72 * 2;   // 55296
    cudaFuncSetAttribute(mma_gemm<128,1>, cudaFuncAttributeMaxDynamicSharedMemorySize, SM128);
    cudaFuncSetAttribute(mma_gemm<128,2>, cudaFuncAttributeMaxDynamicSharedMemorySize, SM128);
    cudaFuncSetAttribute(mma_gemm<64,2>,  cudaFuncAttributeMaxDynamicSharedMemorySize, SM64);
    cudaFuncSetAttribute(score_select_kernel, cudaFuncAttributeMaxDynamicSharedMemorySize, SS_SMEM);

    // 1) conv + LN -> ynorm bf16
    conv_ln_kernel<<<B_*NYk, 256>>>(y, c1w, c1b, c2w, c2b, c3w, c3b, lnw, lnb);

    // 2) bf16 conversions
    cvt_kernel<<<3072, 256>>>(x,  (__nv_bfloat16*)x16,  786432);
    cvt_kernel<<<576,  256>>>(qw, (__nv_bfloat16*)qw16, 147456);
    cvt_kernel<<<1152, 256>>>(kvw,(__nv_bfloat16*)kvw16,294912);
    cvt_kernel<<<576,  256>>>(pw, (__nv_bfloat16*)pw16, 147456);

    // 3) q = x @ q_w^T  -> bf16
    mma_gemm<128,2><<<dim3(6,32,1), 256, SM128>>>(
        (const __nv_bfloat16*)x16, (const __nv_bfloat16*)qw16,
        nullptr, (__nv_bfloat16*)q16, nullptr, nullptr,
        768, 768, 768, 768, 1.0f, 1, 0,0,0,0,0,0);

    // 4) kv = y_norm @ kv_w^T -> bf16
    mma_gemm<128,2><<<dim3(12,32,1), 256, SM128>>>(
        (const __nv_bfloat16*)yn16, (const __nv_bfloat16*)kvw16,
        nullptr, (__nv_bfloat16*)kv16, nullptr, nullptr,
        768, 768, 768, 1536, 1.0f, 1, 0,0,0,0,0,0);

    // 5) V^T
    vtrans_kernel<<<dim3(48,32), 256>>>();

    // 6+7) fused scores + dual top-k + softmax weights -> W (bf16); no S in HBM
    score_select_kernel<<<dim3(32,48), 256, SS_SMEM>>>(pk1, pk2);

    // 8) attn = W @ V^T -> bf16
    mma_gemm<64,2><<<dim3(1,8,48), 256, SM64>>>(
        (const __nv_bfloat16*)W, (const __nv_bfloat16*)vt16,
        nullptr, (__nv_bfloat16*)at16, nullptr, nullptr,
        1024, 1024, 1024, 768, 1.0f, 12,
        (long long)12*1024*1024, (long long)1024*1024,
        (long long)12*64*1024,   (long long)64*1024,
        (long long)1024*768, 64);

    // 9) out = attn @ proj_w^T + proj_b + x
    mma_gemm<128,1><<<dim3(6,32,1), 256, SM128>>>(
        (const __nv_bfloat16*)at16, (const __nv_bfloat16*)pw16,
        out, nullptr, pb, x,
        768, 768, 768, 768, 1.0f, 1, 0,0,0,0,0,0);
}

// round 9
// speedup vs baseline: 1.3546x; 1.3546x over previous
#include <cuda_runtime.h>
#include <cuda_bf16.h>
#include <cstdint>

#define B_  4
#define NXq 1024
#define NYk 1024
#define C_  768
#define H_  12
#define D_  64

// ======================= scratch (static device globals) =======================
__device__ float g_S[12u*1024u*1024u];                        // per-group fp32 scores (reused 4x)
__device__ __align__(16) __nv_bfloat16 g_x16 [B_*NXq*C_];
__device__ __align__(16) __nv_bfloat16 g_yn16[B_*NYk*C_];
__device__ __align__(16) __nv_bfloat16 g_q16 [B_*NXq*C_];
__device__ __align__(16) __nv_bfloat16 g_kv16[B_*NYk*2*C_];
__device__ __align__(16) __nv_bfloat16 g_vt16[48*64*1024];
__device__ __align__(16) __nv_bfloat16 g_W   [48u*1024u*1024u];
__device__ __align__(16) __nv_bfloat16 g_at16[B_*NXq*C_];
__device__ __align__(16) __nv_bfloat16 g_qw16 [C_*C_];
__device__ __align__(16) __nv_bfloat16 g_kvw16[2*C_*C_];
__device__ __align__(16) __nv_bfloat16 g_pw16 [C_*C_];

__device__ __forceinline__ uint32_t smem_u32(const void* p) {
    uint32_t a;
    asm("{ .reg .u64 t; cvta.to.shared.u64 t, %1; cvt.u32.u64 %0, t; }" : "=r"(a) : "l"(p));
    return a;
}
__device__ __forceinline__ void cp16(uint32_t dst, const void* src) {
    asm volatile("cp.async.cg.shared.global [%0], [%1], 16;" :: "r"(dst), "l"(src));
}

// ======================= fused multiscale conv + LayerNorm -> bf16 (4 rows/block) =======================
__global__ void __launch_bounds__(256) conv_ln_kernel(
    const float* __restrict__ y,
    const float* __restrict__ c1w, const float* __restrict__ c1b,
    const float* __restrict__ c2w, const float* __restrict__ c2b,
    const float* __restrict__ c3w, const float* __restrict__ c3b,
    const float* __restrict__ lnw, const float* __restrict__ lnb)
{
    int grp = blockIdx.x;             // 4 batches x 256 row-groups
    int b  = grp >> 8;
    int r0 = (grp & 255) * 4;
    const float* yb = y + (size_t)b * NYk * C_;
    int tid = threadIdx.x, lane = tid & 31, w = tid >> 5;

    float vals[3][4];
    float lsum[4] = {0,0,0,0}, lsq[4] = {0,0,0,0};
    #pragma unroll
    for (int i = 0; i < 3; i++) {
        int c = tid + i * 256;
        float w7[7];
        #pragma unroll
        for (int j = 0; j < 7; j++) w7[j] = c3w[c*7 + j];
        #pragma unroll
        for (int j = 0; j < 5; j++) w7[j+1] += c2w[c*5 + j];
        #pragma unroll
        for (int j = 0; j < 3; j++) w7[j+2] += c1w[c*3 + j];
        float bias = c1b[c] + c2b[c] + c3b[c];
        float yv[10];
        #pragma unroll
        for (int j = 0; j < 10; j++) {
            int nn = r0 - 3 + j;
            yv[j] = (nn >= 0 && nn < NYk) ? yb[(size_t)nn * C_ + c] : 0.f;
        }
        #pragma unroll
        for (int rr = 0; rr < 4; rr++) {
            float acc = bias;
            #pragma unroll
            for (int j = 0; j < 7; j++) acc += w7[j] * yv[rr + j];
            vals[i][rr] = acc;
            lsum[rr] += acc; lsq[rr] += acc * acc;
        }
    }

    __shared__ float sw1[4][8], sw2[4][8];
    __shared__ float smean[4], srstd[4];
    #pragma unroll
    for (int rr = 0; rr < 4; rr++) {
        float a = lsum[rr], q = lsq[rr];
        #pragma unroll
        for (int d = 16; d > 0; d >>= 1) {
            a += __shfl_xor_sync(0xFFFFFFFFu, a, d);
            q += __shfl_xor_sync(0xFFFFFFFFu, q, d);
        }
        if (lane == 0) { sw1[rr][w] = a; sw2[rr][w] = q; }
    }
    __syncthreads();
    if (tid < 4) {
        float a = 0.f, q = 0.f;
        #pragma unroll
        for (int j = 0; j < 8; j++) { a += sw1[tid][j]; q += sw2[tid][j]; }
        float mean = a * (1.0f / C_);
        float var  = q * (1.0f / C_) - mean * mean;
        smean[tid] = mean;
        srstd[tid] = rsqrtf(var + 1e-5f);
    }
    __syncthreads();

    #pragma unroll
    for (int i = 0; i < 3; i++) {
        int c = tid + i * 256;
        float lw = lnw[c], lb = lnb[c];
        #pragma unroll
        for (int rr = 0; rr < 4; rr++) {
            float v = (vals[i][rr] - smean[rr]) * srstd[rr] * lw + lb;
            g_yn16[(size_t)(b*1024 + r0 + rr) * C_ + c] = __float2bfloat16(v);
        }
    }
}

// ======================= merged fp32 -> bf16 convert (all 4 tensors) =======================
#define CV0 786432
#define CV1 (CV0 + 147456)
#define CV2 (CV1 + 294912)
#define CV3 (CV2 + 147456)
__global__ void __launch_bounds__(256) cvt_all_kernel(
    const float* __restrict__ x,  const float* __restrict__ qw,
    const float* __restrict__ kvw, const float* __restrict__ pw)
{
    int i = blockIdx.x * 256 + threadIdx.x;
    if (i >= CV3) return;
    const float* s; __nv_bfloat16* o; int off;
    if (i < CV0)      { s = x;   o = g_x16;   off = i; }
    else if (i < CV1) { s = qw;  o = g_qw16;  off = i - CV0; }
    else if (i < CV2) { s = kvw; o = g_kvw16; off = i - CV1; }
    else              { s = pw;  o = g_pw16;  off = i - CV2; }
    float4 v = ((const float4*)s)[off];
    __nv_bfloat162* O = (__nv_bfloat162*)o;
    O[2*off]   = __halves2bfloat162(__float2bfloat16(v.x), __float2bfloat16(v.y));
    O[2*off+1] = __halves2bfloat162(__float2bfloat16(v.z), __float2bfloat16(v.w));
}

// ======================= V transpose =======================
__global__ void __launch_bounds__(256) vtrans_kernel()
{
    int z  = blockIdx.x;
    int t0 = blockIdx.y * 32;
    int b = z / 12, h = z - b*12;
    __shared__ __nv_bfloat16 sh[64][33];
    int tid = threadIdx.x;
    #pragma unroll
    for (int i = 0; i < 8; i++) {
        int idx = tid + i*256;
        int tok = idx >> 6, d = idx & 63;
        size_t off = ((size_t)(b*1024 + t0 + tok)) * 1536 + 768 + h*64 + d;
        sh[d][tok] = g_kv16[off];
    }
    __syncthreads();
    #pragma unroll
    for (int i = 0; i < 8; i++) {
        int o = tid + i*256;
        int d = o >> 5, c = o & 31;
        size_t off = (size_t)z * 64 * 1024 + (size_t)d * 1024 + t0 + c;
        g_vt16[off] = sh[d][c];
    }
}

// ======================= HMMA GEMM (R5, proven) =======================
template<int NT, int OUTM>
__global__ void __launch_bounds__(256) mma_gemm(
    const __nv_bfloat16* __restrict__ A, const __nv_bfloat16* __restrict__ B,
    float* __restrict__ Co, __nv_bfloat16* __restrict__ Cb,
    const float* __restrict__ bias, const float* __restrict__ res,
    int K, int lda, int ldb, int ldc, float alpha, int HH,
    long long aO, long long aI, long long bO, long long bI,
    long long cO, long long cI)
{
    constexpr int WM  = (NT == 128) ? 2 : 4;
    constexpr int WN  = 8 / WM;
    constexpr int WTM = 128 / WM;
    constexpr int WTN = NT / WN;
    constexpr int MT  = WTM / 16;
    constexpr int NTT = WTN / 8;
    constexpr int PITCH = 72;
    constexpr int ABYTES = 128 * PITCH * 2;
    constexpr int BBYTES = NT  * PITCH * 2;
    constexpr int STAGE  = ABYTES + BBYTES;

    extern __shared__ __align__(16) char dsm[];
    uint32_t smbase = smem_u32(dsm);

    int tid = threadIdx.x, wid = tid >> 5, lane = tid & 31;
    int wm = wid % WM, wn = wid / WM;

    int z = blockIdx.z, zo = z / HH, zi = z - zo * HH;
    A += zo*aO + zi*aI;
    B += zo*bO + zi*bI;
    long long coff = zo*cO + zi*cI;

    long long m0 = (long long)blockIdx.y * 128;
    long long n0 = (long long)blockIdx.x * NT;

    float acc[MT][NTT][4];
    #pragma unroll
    for (int i = 0; i < MT; i++)
        #pragma unroll
        for (int j = 0; j < NTT; j++)
            #pragma unroll
            for (int r = 0; r < 4; r++) acc[i][j][r] = 0.f;

    int nIter = K >> 6;

    uint32_t a_off = ((uint32_t)(wm*WTM + (lane & 15)) * PITCH + ((lane >> 4) << 3)) * 2;
    uint32_t b_off = ABYTES + ((uint32_t)(wn*WTN + (lane & 7)) * PITCH + (((lane >> 3) & 1) << 3)) * 2;

    auto issue = [&](int t) {
        int k0 = t << 6, s = t & 1;
        uint32_t sa = smbase + s * STAGE;
        uint32_t sb = sa + ABYTES;
        #pragma unroll
        for (int i = 0; i < 4; i++) {
            int ch = tid + (i << 8);
            int r = ch >> 3, c = (ch & 7) << 3;
            cp16(sa + (uint32_t)(r*PITCH + c)*2, A + (m0 + r)*lda + k0 + c);
        }
        #pragma unroll
        for (int i = 0; i < NT/32; i++) {
            int ch = tid + (i << 8);
            int r = ch >> 3, c = (ch & 7) << 3;
            cp16(sb + (uint32_t)(r*PITCH + c)*2, B + (n0 + r)*ldb + k0 + c);
        }
        asm volatile("cp.async.commit_group;");
    };

    issue(0);
    for (int t = 0; t < nIter; t++) {
        if (t + 1 < nIter) {
            issue(t + 1);
            asm volatile("cp.async.wait_group 1;");
        } else {
            asm volatile("cp.async.wait_group 0;");
        }
        __syncthreads();
        uint32_t stg = smbase + (uint32_t)(t & 1) * STAGE;
        uint32_t abase = stg + a_off;
        uint32_t bbase = stg + b_off;

        #pragma unroll
        for (int ks = 0; ks < 4; ks++) {
            uint32_t kb = (uint32_t)ks << 5;
            uint32_t af[MT][4];
            #pragma unroll
            for (int mt = 0; mt < MT; mt++) {
                asm volatile("ldmatrix.sync.aligned.m8n8.x4.shared.b16 {%0,%1,%2,%3}, [%4];"
                    : "=r"(af[mt][0]), "=r"(af[mt][1]), "=r"(af[mt][2]), "=r"(af[mt][3])
                    : "r"(abase + (uint32_t)(mt*16*PITCH*2) + kb));
            }
            uint32_t bf[NTT][2];
            #pragma unroll
            for (int nt = 0; nt < NTT; nt++) {
                asm volatile("ldmatrix.sync.aligned.m8n8.x2.shared.b16 {%0,%1}, [%2];"
                    : "=r"(bf[nt][0]), "=r"(bf[nt][1])
                    : "r"(bbase + (uint32_t)(nt*8*PITCH*2) + kb));
            }
            #pragma unroll
            for (int mt = 0; mt < MT; mt++)
                #pragma unroll
                for (int nt = 0; nt < NTT; nt++) {
                    asm volatile(
                        "mma.sync.aligned.m16n8k16.row.col.f32.bf16.bf16.f32 "
                        "{%0,%1,%2,%3}, {%4,%5,%6,%7}, {%8,%9}, {%0,%1,%2,%3};"
                        : "+f"(acc[mt][nt][0]), "+f"(acc[mt][nt][1]),
                          "+f"(acc[mt][nt][2]), "+f"(acc[mt][nt][3])
                        : "r"(af[mt][0]), "r"(af[mt][1]), "r"(af[mt][2]), "r"(af[mt][3]),
                          "r"(bf[nt][0]), "r"(bf[nt][1]));
                }
        }
        __syncthreads();
    }

    int gg = lane >> 2, qq = lane & 3;
    #pragma unroll
    for (int mt = 0; mt < MT; mt++) {
        long long gm = m0 + wm*WTM + mt*16 + gg;
        #pragma unroll
        for (int nt = 0; nt < NTT; nt++) {
            long long gn = n0 + wn*WTN + nt*8 + 2*qq;
            float v0 = acc[mt][nt][0] * alpha;
            float v1 = acc[mt][nt][1] * alpha;
            float v2 = acc[mt][nt][2] * alpha;
            float v3 = acc[mt][nt][3] * alpha;
            long long gi0 = coff + gm * (long long)ldc + gn;
            long long gi1 = gi0 + 8LL * ldc;
            if (OUTM == 0) {
                *(float2*)&Co[gi0] = make_float2(v0, v1);
                *(float2*)&Co[gi1] = make_float2(v2, v3);
            } else if (OUTM == 1) {
                float b0 = bias[gn], b1 = bias[gn + 1];
                float2 r0 = *(const float2*)&res[gi0];
                float2 r1 = *(const float2*)&res[gi1];
                *(float2*)&Co[gi0] = make_float2(v0 + b0 + r0.x, v1 + b1 + r0.y);
                *(float2*)&Co[gi1] = make_float2(v2 + b0 + r1.x, v3 + b1 + r1.y);
            } else {
                *(__nv_bfloat162*)&Cb[gi0] =
                    __halves2bfloat162(__float2bfloat16(v0), __float2bfloat16(v1));
                *(__nv_bfloat162*)&Cb[gi1] =
                    __halves2bfloat162(__float2bfloat16(v2), __float2bfloat16(v3));
            }
        }
    }
}

// ======================= warp-per-row dual top-k select -> W (bf16) =======================
__global__ void __launch_bounds__(256) select_kernel(
    const float* __restrict__ Sbase, __nv_bfloat16* __restrict__ Wbase,
    const int* __restrict__ pk1, const int* __restrict__ pk2)
{
    __shared__ unsigned hist[8][512];

    int tid = threadIdx.x, lane = tid & 31, wid = tid >> 5;
    long long row = (long long)blockIdx.x * 8 + wid;
    const float* Srow = Sbase + row * 1024;

    unsigned u[32];
    unsigned umax = 0u;
    #pragma unroll
    for (int j = 0; j < 8; j++) {
        float4 f = *(const float4*)(Srow + j*128 + lane*4);
        float vv[4] = {f.x, f.y, f.z, f.w};
        #pragma unroll
        for (int e = 0; e < 4; e++) {
            unsigned b = __float_as_uint(vv[e]);
            unsigned k = (b & 0x80000000u) ? ~b : (b | 0x80000000u);
            u[j*4 + e] = k;
            umax = (k > umax) ? k : umax;
        }
    }
    #pragma unroll
    for (int d = 16; d > 0; d >>= 1) {
        unsigned o = __shfl_xor_sync(0xFFFFFFFFu, umax, d);
        umax = (o > umax) ? o : umax;
    }
    float m = (umax & 0x80000000u) ? __uint_as_float(umax & 0x7FFFFFFFu)
                                   : __uint_as_float(~umax);

    int k1 = *pk1, k2 = *pk2;
    unsigned* h0 = hist[wid];
    unsigned* h1 = hist[wid] + 256;

    auto scan1 = [&](const unsigned* h, unsigned pfx, int kk, int sh,
                     unsigned& pout, int& kout) {
        unsigned h8[8];
        #pragma unroll
        for (int i = 0; i < 8; i++) h8[i] = h[lane*8 + i];
        unsigned tot = 0;
        #pragma unroll
        for (int i = 0; i < 8; i++) tot += h8[i];
        unsigned s = tot;
        #pragma unroll
        for (int d = 1; d < 32; d <<= 1) {
            unsigned t = __shfl_down_sync(0xFFFFFFFFu, s, d);
            if (lane + d < 32) s += t;
        }
        unsigned run = s - tot;
        unsigned myp = 0u; int myk = 0; bool found = false;
        #pragma unroll
        for (int i = 7; i >= 0; i--) {
            unsigned cn = run;
            run += h8[i];
            if (!found && run >= (unsigned)kk && cn < (unsigned)kk) {
                found = true;
                myp = pfx | ((unsigned)(lane*8 + i) << sh);
                myk = kk - (int)cn;
            }
        }
        unsigned ball = __ballot_sync(0xFFFFFFFFu, found);
        int src = __ffs(ball) - 1;
        pout = __shfl_sync(0xFFFFFFFFu, myp, src);
        kout = __shfl_sync(0xFFFFFFFFu, myk, src);
    };

    // level 3
    #pragma unroll
    for (int i = 0; i < 8; i++) h0[lane*8 + i] = 0u;
    __syncwarp();
    #pragma unroll
    for (int j = 0; j < 32; j++) atomicAdd(&h0[u[j] >> 24], 1u);
    __syncwarp();
    unsigned p1, p2; int kk1, kk2;
    scan1(h0, 0u, k1, 24, p1, kk1);
    scan1(h0, 0u, k2, 24, p2, kk2);

    // levels 2..0
    #pragma unroll
    for (int lev = 2; lev >= 0; lev--) {
        int sh = lev * 8;
        unsigned himask = 0xFFFFFFFFu << (sh + 8);
        bool same = (p1 == p2);
        __syncwarp();
        #pragma unroll
        for (int i = 0; i < 16; i++) hist[wid][lane*16 + i] = 0u;
        __syncwarp();
        #pragma unroll
        for (int j = 0; j < 32; j++) {
            unsigned uu = u[j];
            if (((uu ^ p1) & himask) == 0u) atomicAdd(&h0[(uu >> sh) & 255u], 1u);
            if (!same && ((uu ^ p2) & himask) == 0u) atomicAdd(&h1[(uu >> sh) & 255u], 1u);
        }
        __syncwarp();
        unsigned p1o = p1, p2o = p2;
        scan1(h0, p1o, kk1, sh, p1, kk1);
        scan1(same ? h0 : h1, p2o, kk2, sh, p2, kk2);
    }

    // masked Z sums
    float ev[32];
    float z1 = 0.f, z2 = 0.f;
    #pragma unroll
    for (int j = 0; j < 32; j++) {
        unsigned uu = u[j];
        float v = (uu & 0x80000000u) ? __uint_as_float(uu & 0x7FFFFFFFu)
                                     : __uint_as_float(~uu);
        float e = __expf(v - m);
        ev[j] = e;
        if (uu >= p1) z1 += e;
        if (uu >= p2) z2 += e;
    }
    #pragma unroll
    for (int d = 16; d > 0; d >>= 1) {
        z1 += __shfl_xor_sync(0xFFFFFFFFu, z1, d);
        z2 += __shfl_xor_sync(0xFFFFFFFFu, z2, d);
    }
    float c1 = 0.6f / z1;
    float c2 = 0.4f / z2;

    __nv_bfloat16* Wrow = Wbase + row * 1024;
    #pragma unroll
    for (int j = 0; j < 8; j++) {
        __nv_bfloat16 o4[4];
        #pragma unroll
        for (int e = 0; e < 4; e++) {
            unsigned uu = u[j*4 + e];
            float x = ev[j*4 + e];
            float w = x * ((uu >= p1) ? c1 : 0.f) + x * ((uu >= p2) ? c2 : 0.f);
            o4[e] = __float2bfloat16(w);
        }
        *(uint2*)&Wrow[j*128 + lane*4] = *(uint2*)o4;
    }
}

// ======================= launch =======================
extern "C" void kernel_launch(void* const* d_in, const int* in_sizes, int n_in,
                              void* d_out, int out_size)
{
    const float* x   = (const float*)d_in[0];
    const float* y   = (const float*)d_in[1];
    const float* c1w = (const float*)d_in[2];
    const float* c1b = (const float*)d_in[3];
    const float* c2w = (const float*)d_in[4];
    const float* c2b = (const float*)d_in[5];
    const float* c3w = (const float*)d_in[6];
    const float* c3b = (const float*)d_in[7];
    const float* lnw = (const float*)d_in[8];
    const float* lnb = (const float*)d_in[9];
    const float* qw  = (const float*)d_in[10];
    const float* kvw = (const float*)d_in[11];
    const float* pw  = (const float*)d_in[12];
    const float* pb  = (const float*)d_in[13];
    const int*   pk1 = (const int*)d_in[14];
    const int*   pk2 = (const int*)d_in[15];
    float* out = (float*)d_out;

    #define SYM(p, g) void* p; cudaGetSymbolAddress(&p, g)
    SYM(S, g_S);
    SYM(x16, g_x16);   SYM(yn16, g_yn16);
    SYM(q16, g_q16);   SYM(kv16, g_kv16);
    SYM(vt16, g_vt16); SYM(W, g_W);
    SYM(at16, g_at16);
    SYM(qw16, g_qw16); SYM(kvw16, g_kvw16); SYM(pw16, g_pw16);
    #undef SYM

    const int SM128 = 2 * (128 + 128) * 72 * 2;   // 73728
    const int SM64  = 2 * (128 + 64)  * 72 * 2;   // 55296
    cudaFuncSetAttribute(mma_gemm<128,0>, cudaFuncAttributeMaxDynamicSharedMemorySize, SM128);
    cudaFuncSetAttribute(mma_gemm<128,1>, cudaFuncAttributeMaxDynamicSharedMemorySize, SM128);
    cudaFuncSetAttribute(mma_gemm<128,2>, cudaFuncAttributeMaxDynamicSharedMemorySize, SM128);
    cudaFuncSetAttribute(mma_gemm<64,2>,  cudaFuncAttributeMaxDynamicSharedMemorySize, SM64);

    // 1) conv + LN -> ynorm bf16 (4 rows per block)
    conv_ln_kernel<<<1024, 256>>>(y, c1w, c1b, c2w, c2b, c3w, c3b, lnw, lnb);

    // 2) merged bf16 conversions
    cvt_all_kernel<<<(CV3 + 255)/256, 256>>>(x, qw, kvw, pw);

    // 3) q = x @ q_w^T  -> bf16
    mma_gemm<128,2><<<dim3(6,32,1), 256, SM128>>>(
        (const __nv_bfloat16*)x16, (const __nv_bfloat16*)qw16,
        nullptr, (__nv_bfloat16*)q16, nullptr, nullptr,
        768, 768, 768, 768, 1.0f, 1, 0,0,0,0,0,0);

    // 4) kv = y_norm @ kv_w^T -> bf16
    mma_gemm<128,2><<<dim3(12,32,1), 256, SM128>>>(
        (const __nv_bfloat16*)yn16, (const __nv_bfloat16*)kvw16,
        nullptr, (__nv_bfloat16*)kv16, nullptr, nullptr,
        768, 768, 768, 1536, 1.0f, 1, 0,0,0,0,0,0);

    // 5) V^T
    vtrans_kernel<<<dim3(48,32), 256>>>();

    // 6+7) per-batch groups: score GEMM -> S (L2-resident, reused) -> select -> W
    for (int g = 0; g < 4; g++) {
        const __nv_bfloat16* qg  = (const __nv_bfloat16*)q16  + (size_t)g * 1024 * 768;
        const __nv_bfloat16* kvg = (const __nv_bfloat16*)kv16 + (size_t)g * 1024 * 1536;
        __nv_bfloat16* Wg = (__nv_bfloat16*)W + (size_t)g * 12 * 1024 * 1024;

        mma_gemm<128,0><<<dim3(8,8,12), 256, SM128>>>(
            qg, kvg, (float*)S, nullptr, nullptr, nullptr,
            64, 768, 1536, 1024, 0.125f, 12,
            0, 64, 0, 64, 0, (long long)1024*1024);

        select_kernel<<<12*1024/8, 256>>>((const float*)S, Wg, pk1, pk2);
    }

    // 8) attn = W @ V^T -> bf16 (combined, all 48 heads)
    mma_gemm<64,2><<<dim3(1,8,48), 256, SM64>>>(
        (const __nv_bfloat16*)W, (const __nv_bfloat16*)vt16,
        nullptr, (__nv_bfloat16*)at16, nullptr, nullptr,
        1024, 1024, 1024, 768, 1.0f, 12,
        (long long)12*1024*1024, (long long)1024*1024,
        (long long)12*64*1024,   (long long)64*1024,
        (long long)1024*768, 64);

    // 9) out = attn @ proj_w^T + proj_b + x
    mma_gemm<128,1><<<dim3(6,32,1), 256, SM128>>>(
        (const __nv_bfloat16*)at16, (const __nv_bfloat16*)pw16,
        out, nullptr, pb, x,
        768, 768, 768, 768, 1.0f, 1, 0,0,0,0,0,0);
}

// round 10
// speedup vs baseline: 1.3600x; 1.0040x over previous
#include <cuda_runtime.h>
#include <cuda_bf16.h>
#include <cstdint>

#define B_  4
#define NXq 1024
#define NYk 1024
#define C_  768
#define H_  12
#define D_  64

// ======================= scratch (static device globals) =======================
__device__ float g_S[12u*1024u*1024u];                        // per-group fp32 scores (reused 4x)
__device__ __align__(16) __nv_bfloat16 g_x16 [B_*NXq*C_];
__device__ __align__(16) __nv_bfloat16 g_yn16[B_*NYk*C_];
__device__ __align__(16) __nv_bfloat16 g_q16 [B_*NXq*C_];
__device__ __align__(16) __nv_bfloat16 g_kv16[B_*NYk*2*C_];
__device__ __align__(16) __nv_bfloat16 g_vt16[48*64*1024];
__device__ __align__(16) __nv_bfloat16 g_W   [48u*1024u*1024u];
__device__ __align__(16) __nv_bfloat16 g_at16[B_*NXq*C_];
__device__ __align__(16) __nv_bfloat16 g_qw16 [C_*C_];
__device__ __align__(16) __nv_bfloat16 g_kvw16[2*C_*C_];
__device__ __align__(16) __nv_bfloat16 g_pw16 [C_*C_];

__device__ __forceinline__ uint32_t smem_u32(const void* p) {
    uint32_t a;
    asm("{ .reg .u64 t; cvta.to.shared.u64 t, %1; cvt.u32.u64 %0, t; }" : "=r"(a) : "l"(p));
    return a;
}
__device__ __forceinline__ void cp16(uint32_t dst, const void* src) {
    asm volatile("cp.async.cg.shared.global [%0], [%1], 16;" :: "r"(dst), "l"(src));
}

// ======================= fused multiscale conv + LayerNorm -> bf16 (4 rows/block) =======================
__global__ void __launch_bounds__(256) conv_ln_kernel(
    const float* __restrict__ y,
    const float* __restrict__ c1w, const float* __restrict__ c1b,
    const float* __restrict__ c2w, const float* __restrict__ c2b,
    const float* __restrict__ c3w, const float* __restrict__ c3b,
    const float* __restrict__ lnw, const float* __restrict__ lnb)
{
    int grp = blockIdx.x;
    int b  = grp >> 8;
    int r0 = (grp & 255) * 4;
    const float* yb = y + (size_t)b * NYk * C_;
    int tid = threadIdx.x, lane = tid & 31, w = tid >> 5;

    float vals[3][4];
    float lsum[4] = {0,0,0,0}, lsq[4] = {0,0,0,0};
    #pragma unroll
    for (int i = 0; i < 3; i++) {
        int c = tid + i * 256;
        float w7[7];
        #pragma unroll
        for (int j = 0; j < 7; j++) w7[j] = c3w[c*7 + j];
        #pragma unroll
        for (int j = 0; j < 5; j++) w7[j+1] += c2w[c*5 + j];
        #pragma unroll
        for (int j = 0; j < 3; j++) w7[j+2] += c1w[c*3 + j];
        float bias = c1b[c] + c2b[c] + c3b[c];
        float yv[10];
        #pragma unroll
        for (int j = 0; j < 10; j++) {
            int nn = r0 - 3 + j;
            yv[j] = (nn >= 0 && nn < NYk) ? yb[(size_t)nn * C_ + c] : 0.f;
        }
        #pragma unroll
        for (int rr = 0; rr < 4; rr++) {
            float acc = bias;
            #pragma unroll
            for (int j = 0; j < 7; j++) acc += w7[j] * yv[rr + j];
            vals[i][rr] = acc;
            lsum[rr] += acc; lsq[rr] += acc * acc;
        }
    }

    __shared__ float sw1[4][8], sw2[4][8];
    __shared__ float smean[4], srstd[4];
    #pragma unroll
    for (int rr = 0; rr < 4; rr++) {
        float a = lsum[rr], q = lsq[rr];
        #pragma unroll
        for (int d = 16; d > 0; d >>= 1) {
            a += __shfl_xor_sync(0xFFFFFFFFu, a, d);
            q += __shfl_xor_sync(0xFFFFFFFFu, q, d);
        }
        if (lane == 0) { sw1[rr][w] = a; sw2[rr][w] = q; }
    }
    __syncthreads();
    if (tid < 4) {
        float a = 0.f, q = 0.f;
        #pragma unroll
        for (int j = 0; j < 8; j++) { a += sw1[tid][j]; q += sw2[tid][j]; }
        float mean = a * (1.0f / C_);
        float var  = q * (1.0f / C_) - mean * mean;
        smean[tid] = mean;
        srstd[tid] = rsqrtf(var + 1e-5f);
    }
    __syncthreads();

    #pragma unroll
    for (int i = 0; i < 3; i++) {
        int c = tid + i * 256;
        float lw = lnw[c], lb = lnb[c];
        #pragma unroll
        for (int rr = 0; rr < 4; rr++) {
            float v = (vals[i][rr] - smean[rr]) * srstd[rr] * lw + lb;
            g_yn16[(size_t)(b*1024 + r0 + rr) * C_ + c] = __float2bfloat16(v);
        }
    }
}

// ======================= merged fp32 -> bf16 convert =======================
#define CV0 786432
#define CV1 (CV0 + 147456)
#define CV2 (CV1 + 294912)
#define CV3 (CV2 + 147456)
__global__ void __launch_bounds__(256) cvt_all_kernel(
    const float* __restrict__ x,  const float* __restrict__ qw,
    const float* __restrict__ kvw, const float* __restrict__ pw)
{
    int i = blockIdx.x * 256 + threadIdx.x;
    if (i >= CV3) return;
    const float* s; __nv_bfloat16* o; int off;
    if (i < CV0)      { s = x;   o = g_x16;   off = i; }
    else if (i < CV1) { s = qw;  o = g_qw16;  off = i - CV0; }
    else if (i < CV2) { s = kvw; o = g_kvw16; off = i - CV1; }
    else              { s = pw;  o = g_pw16;  off = i - CV2; }
    float4 v = ((const float4*)s)[off];
    __nv_bfloat162* O = (__nv_bfloat162*)o;
    O[2*off]   = __halves2bfloat162(__float2bfloat16(v.x), __float2bfloat16(v.y));
    O[2*off+1] = __halves2bfloat162(__float2bfloat16(v.z), __float2bfloat16(v.w));
}

// ======================= V transpose =======================
__global__ void __launch_bounds__(256) vtrans_kernel()
{
    int z  = blockIdx.x;
    int t0 = blockIdx.y * 32;
    int b = z / 12, h = z - b*12;
    __shared__ __nv_bfloat16 sh[64][33];
    int tid = threadIdx.x;
    #pragma unroll
    for (int i = 0; i < 8; i++) {
        int idx = tid + i*256;
        int tok = idx >> 6, d = idx & 63;
        size_t off = ((size_t)(b*1024 + t0 + tok)) * 1536 + 768 + h*64 + d;
        sh[d][tok] = g_kv16[off];
    }
    __syncthreads();
    #pragma unroll
    for (int i = 0; i < 8; i++) {
        int o = tid + i*256;
        int d = o >> 5, c = o & 31;
        size_t off = (size_t)z * 64 * 1024 + (size_t)d * 1024 + t0 + c;
        g_vt16[off] = sh[d][c];
    }
}

// ======================= HMMA GEMM: 3-stage cp.async ring, 1 barrier/iter, x4 B-ldmatrix =======================
template<int NT, int OUTM>
__global__ void __launch_bounds__(256) mma_gemm(
    const __nv_bfloat16* __restrict__ A, const __nv_bfloat16* __restrict__ B,
    float* __restrict__ Co, __nv_bfloat16* __restrict__ Cb,
    const float* __restrict__ bias, const float* __restrict__ res,
    int K, int lda, int ldb, int ldc, float alpha, int HH,
    long long aO, long long aI, long long bO, long long bI,
    long long cO, long long cI)
{
    constexpr int WM  = (NT == 128) ? 2 : 4;
    constexpr int WN  = 8 / WM;
    constexpr int WTM = 128 / WM;
    constexpr int WTN = NT / WN;
    constexpr int MT  = WTM / 16;
    constexpr int NTT = WTN / 8;
    constexpr int PITCH = 72;
    constexpr int ABYTES = 128 * PITCH * 2;
    constexpr int BBYTES = NT  * PITCH * 2;
    constexpr int STAGE  = ABYTES + BBYTES;

    extern __shared__ __align__(16) char dsm[];
    uint32_t smbase = smem_u32(dsm);

    int tid = threadIdx.x, wid = tid >> 5, lane = tid & 31;
    int wm = wid % WM, wn = wid / WM;

    int z = blockIdx.z, zo = z / HH, zi = z - zo * HH;
    A += zo*aO + zi*aI;
    B += zo*bO + zi*bI;
    long long coff = zo*cO + zi*cI;

    long long m0 = (long long)blockIdx.y * 128;
    long long n0 = (long long)blockIdx.x * NT;

    float acc[MT][NTT][4];
    #pragma unroll
    for (int i = 0; i < MT; i++)
        #pragma unroll
        for (int j = 0; j < NTT; j++)
            #pragma unroll
            for (int r = 0; r < 4; r++) acc[i][j][r] = 0.f;

    int nIter = K >> 6;

    uint32_t a_off = ((uint32_t)(wm*WTM + (lane & 15)) * PITCH + ((lane >> 4) << 3)) * 2;
    // x4 B-fragment addressing: lane groups 0/1 -> nt rows k0/k8; groups 2/3 -> nt+1 rows k0/k8
    uint32_t b_off4 = ABYTES +
        ((uint32_t)(wn*WTN + (lane & 7) + ((lane >> 4) & 1) * 8) * PITCH
         + (((lane >> 3) & 1) << 3)) * 2;

    auto issue = [&](int t) {
        int k0 = t << 6, s = t % 3;
        uint32_t sa = smbase + s * STAGE;
        uint32_t sb = sa + ABYTES;
        #pragma unroll
        for (int i = 0; i < 4; i++) {
            int ch = tid + (i << 8);
            int r = ch >> 3, c = (ch & 7) << 3;
            cp16(sa + (uint32_t)(r*PITCH + c)*2, A + (m0 + r)*lda + k0 + c);
        }
        #pragma unroll
        for (int i = 0; i < NT/32; i++) {
            int ch = tid + (i << 8);
            int r = ch >> 3, c = (ch & 7) << 3;
            cp16(sb + (uint32_t)(r*PITCH + c)*2, B + (n0 + r)*ldb + k0 + c);
        }
        asm volatile("cp.async.commit_group;");
    };

    issue(0);
    if (nIter > 1) issue(1);
    for (int t = 0; t < nIter; t++) {
        if (t + 2 <= nIter) {
            asm volatile("cp.async.wait_group 1;");
        } else {
            asm volatile("cp.async.wait_group 0;");
        }
        __syncthreads();
        uint32_t stg = smbase + (uint32_t)(t % 3) * STAGE;
        uint32_t abase = stg + a_off;
        uint32_t bbase = stg + b_off4;

        #pragma unroll
        for (int ks = 0; ks < 4; ks++) {
            uint32_t kb = (uint32_t)ks << 5;
            uint32_t af[MT][4];
            #pragma unroll
            for (int mt = 0; mt < MT; mt++) {
                asm volatile("ldmatrix.sync.aligned.m8n8.x4.shared.b16 {%0,%1,%2,%3}, [%4];"
                    : "=r"(af[mt][0]), "=r"(af[mt][1]), "=r"(af[mt][2]), "=r"(af[mt][3])
                    : "r"(abase + (uint32_t)(mt*16*PITCH*2) + kb));
            }
            uint32_t bf[NTT][2];
            #pragma unroll
            for (int np = 0; np < NTT/2; np++) {
                asm volatile("ldmatrix.sync.aligned.m8n8.x4.shared.b16 {%0,%1,%2,%3}, [%4];"
                    : "=r"(bf[2*np][0]), "=r"(bf[2*np][1]),
                      "=r"(bf[2*np+1][0]), "=r"(bf[2*np+1][1])
                    : "r"(bbase + (uint32_t)(np*16*PITCH*2) + kb));
            }
            #pragma unroll
            for (int mt = 0; mt < MT; mt++)
                #pragma unroll
                for (int nt = 0; nt < NTT; nt++) {
                    asm volatile(
                        "mma.sync.aligned.m16n8k16.row.col.f32.bf16.bf16.f32 "
                        "{%0,%1,%2,%3}, {%4,%5,%6,%7}, {%8,%9}, {%0,%1,%2,%3};"
                        : "+f"(acc[mt][nt][0]), "+f"(acc[mt][nt][1]),
                          "+f"(acc[mt][nt][2]), "+f"(acc[mt][nt][3])
                        : "r"(af[mt][0]), "r"(af[mt][1]), "r"(af[mt][2]), "r"(af[mt][3]),
                          "r"(bf[nt][0]), "r"(bf[nt][1]));
                }
        }
        if (t + 2 < nIter) issue(t + 2);
    }

    int gg = lane >> 2, qq = lane & 3;
    #pragma unroll
    for (int mt = 0; mt < MT; mt++) {
        long long gm = m0 + wm*WTM + mt*16 + gg;
        #pragma unroll
        for (int nt = 0; nt < NTT; nt++) {
            long long gn = n0 + wn*WTN + nt*8 + 2*qq;
            float v0 = acc[mt][nt][0] * alpha;
            float v1 = acc[mt][nt][1] * alpha;
            float v2 = acc[mt][nt][2] * alpha;
            float v3 = acc[mt][nt][3] * alpha;
            long long gi0 = coff + gm * (long long)ldc + gn;
            long long gi1 = gi0 + 8LL * ldc;
            if (OUTM == 0) {
                *(float2*)&Co[gi0] = make_float2(v0, v1);
                *(float2*)&Co[gi1] = make_float2(v2, v3);
            } else if (OUTM == 1) {
                float b0 = bias[gn], b1 = bias[gn + 1];
                float2 r0 = *(const float2*)&res[gi0];
                float2 r1 = *(const float2*)&res[gi1];
                *(float2*)&Co[gi0] = make_float2(v0 + b0 + r0.x, v1 + b1 + r0.y);
                *(float2*)&Co[gi1] = make_float2(v2 + b0 + r1.x, v3 + b1 + r1.y);
            } else {
                *(__nv_bfloat162*)&Cb[gi0] =
                    __halves2bfloat162(__float2bfloat16(v0), __float2bfloat16(v1));
                *(__nv_bfloat162*)&Cb[gi1] =
                    __halves2bfloat162(__float2bfloat16(v2), __float2bfloat16(v3));
            }
        }
    }
}

// ======================= warp-per-row dual top-k select -> W (bf16) =======================
__global__ void __launch_bounds__(256) select_kernel(
    const float* __restrict__ Sbase, __nv_bfloat16* __restrict__ Wbase,
    const int* __restrict__ pk1, const int* __restrict__ pk2)
{
    __shared__ unsigned hist[8][512];

    int tid = threadIdx.x, lane = tid & 31, wid = tid >> 5;
    long long row = (long long)blockIdx.x * 8 + wid;
    const float* Srow = Sbase + row * 1024;

    unsigned u[32];
    unsigned umax = 0u;
    #pragma unroll
    for (int j = 0; j < 8; j++) {
        float4 f = *(const float4*)(Srow + j*128 + lane*4);
        float vv[4] = {f.x, f.y, f.z, f.w};
        #pragma unroll
        for (int e = 0; e < 4; e++) {
            unsigned b = __float_as_uint(vv[e]);
            unsigned k = (b & 0x80000000u) ? ~b : (b | 0x80000000u);
            u[j*4 + e] = k;
            umax = (k > umax) ? k : umax;
        }
    }
    #pragma unroll
    for (int d = 16; d > 0; d >>= 1) {
        unsigned o = __shfl_xor_sync(0xFFFFFFFFu, umax, d);
        umax = (o > umax) ? o : umax;
    }
    float m = (umax & 0x80000000u) ? __uint_as_float(umax & 0x7FFFFFFFu)
                                   : __uint_as_float(~umax);

    int k1 = *pk1, k2 = *pk2;
    unsigned* h0 = hist[wid];
    unsigned* h1 = hist[wid] + 256;

    auto scan1 = [&](const unsigned* h, unsigned pfx, int kk, int sh,
                     unsigned& pout, int& kout) {
        unsigned h8[8];
        #pragma unroll
        for (int i = 0; i < 8; i++) h8[i] = h[lane*8 + i];
        unsigned tot = 0;
        #pragma unroll
        for (int i = 0; i < 8; i++) tot += h8[i];
        unsigned s = tot;
        #pragma unroll
        for (int d = 1; d < 32; d <<= 1) {
            unsigned t = __shfl_down_sync(0xFFFFFFFFu, s, d);
            if (lane + d < 32) s += t;
        }
        unsigned run = s - tot;
        unsigned myp = 0u; int myk = 0; bool found = false;
        #pragma unroll
        for (int i = 7; i >= 0; i--) {
            unsigned cn = run;
            run += h8[i];
            if (!found && run >= (unsigned)kk && cn < (unsigned)kk) {
                found = true;
                myp = pfx | ((unsigned)(lane*8 + i) << sh);
                myk = kk - (int)cn;
            }
        }
        unsigned ball = __ballot_sync(0xFFFFFFFFu, found);
        int src = __ffs(ball) - 1;
        pout = __shfl_sync(0xFFFFFFFFu, myp, src);
        kout = __shfl_sync(0xFFFFFFFFu, myk, src);
    };

    // level 3
    #pragma unroll
    for (int i = 0; i < 8; i++) h0[lane*8 + i] = 0u;
    __syncwarp();
    #pragma unroll
    for (int j = 0; j < 32; j++) atomicAdd(&h0[u[j] >> 24], 1u);
    __syncwarp();
    unsigned p1, p2; int kk1, kk2;
    scan1(h0, 0u, k1, 24, p1, kk1);
    scan1(h0, 0u, k2, 24, p2, kk2);

    // levels 2..0
    #pragma unroll
    for (int lev = 2; lev >= 0; lev--) {
        int sh = lev * 8;
        unsigned himask = 0xFFFFFFFFu << (sh + 8);
        bool same = (p1 == p2);
        __syncwarp();
        #pragma unroll
        for (int i = 0; i < 16; i++) hist[wid][lane*16 + i] = 0u;
        __syncwarp();
        #pragma unroll
        for (int j = 0; j < 32; j++) {
            unsigned uu = u[j];
            if (((uu ^ p1) & himask) == 0u) atomicAdd(&h0[(uu >> sh) & 255u], 1u);
            if (!same && ((uu ^ p2) & himask) == 0u) atomicAdd(&h1[(uu >> sh) & 255u], 1u);
        }
        __syncwarp();
        unsigned p1o = p1, p2o = p2;
        scan1(h0, p1o, kk1, sh, p1, kk1);
        scan1(same ? h0 : h1, p2o, kk2, sh, p2, kk2);
    }

    // masked Z sums
    float ev[32];
    float z1 = 0.f, z2 = 0.f;
    #pragma unroll
    for (int j = 0; j < 32; j++) {
        unsigned uu = u[j];
        float v = (uu & 0x80000000u) ? __uint_as_float(uu & 0x7FFFFFFFu)
                                     : __uint_as_float(~uu);
        float e = __expf(v - m);
        ev[j] = e;
        if (uu >= p1) z1 += e;
        if (uu >= p2) z2 += e;
    }
    #pragma unroll
    for (int d = 16; d > 0; d >>= 1) {
        z1 += __shfl_xor_sync(0xFFFFFFFFu, z1, d);
        z2 += __shfl_xor_sync(0xFFFFFFFFu, z2, d);
    }
    float c1 = 0.6f / z1;
    float c2 = 0.4f / z2;

    __nv_bfloat16* Wrow = Wbase + row * 1024;
    #pragma unroll
    for (int j = 0; j < 8; j++) {
        __nv_bfloat16 o4[4];
        #pragma unroll
        for (int e = 0; e < 4; e++) {
            unsigned uu = u[j*4 + e];
            float x = ev[j*4 + e];
            float w = x * ((uu >= p1) ? c1 : 0.f) + x * ((uu >= p2) ? c2 : 0.f);
            o4[e] = __float2bfloat16(w);
        }
        *(uint2*)&Wrow[j*128 + lane*4] = *(uint2*)o4;
    }
}

// ======================= launch =======================
extern "C" void kernel_launch(void* const* d_in, const int* in_sizes, int n_in,
                              void* d_out, int out_size)
{
    const float* x   = (const float*)d_in[0];
    const float* y   = (const float*)d_in[1];
    const float* c1w = (const float*)d_in[2];
    const float* c1b = (const float*)d_in[3];
    const float* c2w = (const float*)d_in[4];
    const float* c2b = (const float*)d_in[5];
    const float* c3w = (const float*)d_in[6];
    const float* c3b = (const float*)d_in[7];
    const float* lnw = (const float*)d_in[8];
    const float* lnb = (const float*)d_in[9];
    const float* qw  = (const float*)d_in[10];
    const float* kvw = (const float*)d_in[11];
    const float* pw  = (const float*)d_in[12];
    const float* pb  = (const float*)d_in[13];
    const int*   pk1 = (const int*)d_in[14];
    const int*   pk2 = (const int*)d_in[15];
    float* out = (float*)d_out;

    #define SYM(p, g) void* p; cudaGetSymbolAddress(&p, g)
    SYM(S, g_S);
    SYM(x16, g_x16);   SYM(yn16, g_yn16);
    SYM(q16, g_q16);   SYM(kv16, g_kv16);
    SYM(vt16, g_vt16); SYM(W, g_W);
    SYM(at16, g_at16);
    SYM(qw16, g_qw16); SYM(kvw16, g_kvw16); SYM(pw16, g_pw16);
    #undef SYM

    const int SM128 = 3 * (128 + 128) * 72 * 2;   // 110592
    const int SM64  = 3 * (128 + 64)  * 72 * 2;   // 82944
    cudaFuncSetAttribute(mma_gemm<128,0>, cudaFuncAttributeMaxDynamicSharedMemorySize, SM128);
    cudaFuncSetAttribute(mma_gemm<128,1>, cudaFuncAttributeMaxDynamicSharedMemorySize, SM128);
    cudaFuncSetAttribute(mma_gemm<128,2>, cudaFuncAttributeMaxDynamicSharedMemorySize, SM128);
    cudaFuncSetAttribute(mma_gemm<64,2>,  cudaFuncAttributeMaxDynamicSharedMemorySize, SM64);

    // 1) conv + LN -> ynorm bf16
    conv_ln_kernel<<<1024, 256>>>(y, c1w, c1b, c2w, c2b, c3w, c3b, lnw, lnb);

    // 2) merged bf16 conversions
    cvt_all_kernel<<<(CV3 + 255)/256, 256>>>(x, qw, kvw, pw);

    // 3) q = x @ q_w^T  -> bf16
    mma_gemm<128,2><<<dim3(6,32,1), 256, SM128>>>(
        (const __nv_bfloat16*)x16, (const __nv_bfloat16*)qw16,
        nullptr, (__nv_bfloat16*)q16, nullptr, nullptr,
        768, 768, 768, 768, 1.0f, 1, 0,0,0,0,0,0);

    // 4) kv = y_norm @ kv_w^T -> bf16
    mma_gemm<128,2><<<dim3(12,32,1), 256, SM128>>>(
        (const __nv_bfloat16*)yn16, (const __nv_bfloat16*)kvw16,
        nullptr, (__nv_bfloat16*)kv16, nullptr, nullptr,
        768, 768, 768, 1536, 1.0f, 1, 0,0,0,0,0,0);

    // 5) V^T
    vtrans_kernel<<<dim3(48,32), 256>>>();

    // 6+7) per-batch groups: score GEMM -> S (L2-resident) -> select -> W
    for (int g = 0; g < 4; g++) {
        const __nv_bfloat16* qg  = (const __nv_bfloat16*)q16  + (size_t)g * 1024 * 768;
        const __nv_bfloat16* kvg = (const __nv_bfloat16*)kv16 + (size_t)g * 1024 * 1536;
        __nv_bfloat16* Wg = (__nv_bfloat16*)W + (size_t)g * 12 * 1024 * 1024;

        mma_gemm<128,0><<<dim3(8,8,12), 256, SM128>>>(
            qg, kvg, (float*)S, nullptr, nullptr, nullptr,
            64, 768, 1536, 1024, 0.125f, 12,
            0, 64, 0, 64, 0, (long long)1024*1024);

        select_kernel<<<12*1024/8, 256>>>((const float*)S, Wg, pk1, pk2);
    }

    // 8) attn = W @ V^T -> bf16
    mma_gemm<64,2><<<dim3(1,8,48), 256, SM64>>>(
        (const __nv_bfloat16*)W, (const __nv_bfloat16*)vt16,
        nullptr, (__nv_bfloat16*)at16, nullptr, nullptr,
        1024, 1024, 1024, 768, 1.0f, 12,
        (long long)12*1024*1024, (long long)1024*1024,
        (long long)12*64*1024,   (long long)64*1024,
        (long long)1024*768, 64);

    // 9) out = attn @ proj_w^T + proj_b + x
    mma_gemm<128,1><<<dim3(6,32,1), 256, SM128>>>(
        (const __nv_bfloat16*)at16, (const __nv_bfloat16*)pw16,
        out, nullptr, pb, x,
        768, 768, 768, 768, 1.0f, 1, 0,0,0,0,0,0);
}

// round 11
// speedup vs baseline: 1.4755x; 1.0849x over previous
#include <cuda_runtime.h>
#include <cuda_bf16.h>
#include <cstdint>

#define B_  4
#define NXq 1024
#define NYk 1024
#define C_  768
#define H_  12
#define D_  64

// ======================= scratch (static device globals) =======================
__device__ float g_S[2][12u*1024u*1024u];                     // double-buffered group scores
__device__ __align__(16) __nv_bfloat16 g_x16 [B_*NXq*C_];
__device__ __align__(16) __nv_bfloat16 g_yn16[B_*NYk*C_];
__device__ __align__(16) __nv_bfloat16 g_q16 [B_*NXq*C_];
__device__ __align__(16) __nv_bfloat16 g_kv16[B_*NYk*2*C_];
__device__ __align__(16) __nv_bfloat16 g_vt16[48*64*1024];
__device__ __align__(16) __nv_bfloat16 g_W   [48u*1024u*1024u];
__device__ __align__(16) __nv_bfloat16 g_at16[B_*NXq*C_];
__device__ __align__(16) __nv_bfloat16 g_qw16 [C_*C_];
__device__ __align__(16) __nv_bfloat16 g_kvw16[2*C_*C_];
__device__ __align__(16) __nv_bfloat16 g_pw16 [C_*C_];

__device__ __forceinline__ uint32_t smem_u32(const void* p) {
    uint32_t a;
    asm("{ .reg .u64 t; cvta.to.shared.u64 t, %1; cvt.u32.u64 %0, t; }" : "=r"(a) : "l"(p));
    return a;
}
__device__ __forceinline__ void cp16(uint32_t dst, const void* src) {
    asm volatile("cp.async.cg.shared.global [%0], [%1], 16;" :: "r"(dst), "l"(src));
}

// ======================= fused multiscale conv + LayerNorm -> bf16 (4 rows/block) =======================
__global__ void __launch_bounds__(256) conv_ln_kernel(
    const float* __restrict__ y,
    const float* __restrict__ c1w, const float* __restrict__ c1b,
    const float* __restrict__ c2w, const float* __restrict__ c2b,
    const float* __restrict__ c3w, const float* __restrict__ c3b,
    const float* __restrict__ lnw, const float* __restrict__ lnb)
{
    int grp = blockIdx.x;
    int b  = grp >> 8;
    int r0 = (grp & 255) * 4;
    const float* yb = y + (size_t)b * NYk * C_;
    int tid = threadIdx.x, lane = tid & 31, w = tid >> 5;

    float vals[3][4];
    float lsum[4] = {0,0,0,0}, lsq[4] = {0,0,0,0};
    #pragma unroll
    for (int i = 0; i < 3; i++) {
        int c = tid + i * 256;
        float w7[7];
        #pragma unroll
        for (int j = 0; j < 7; j++) w7[j] = c3w[c*7 + j];
        #pragma unroll
        for (int j = 0; j < 5; j++) w7[j+1] += c2w[c*5 + j];
        #pragma unroll
        for (int j = 0; j < 3; j++) w7[j+2] += c1w[c*3 + j];
        float bias = c1b[c] + c2b[c] + c3b[c];
        float yv[10];
        #pragma unroll
        for (int j = 0; j < 10; j++) {
            int nn = r0 - 3 + j;
            yv[j] = (nn >= 0 && nn < NYk) ? yb[(size_t)nn * C_ + c] : 0.f;
        }
        #pragma unroll
        for (int rr = 0; rr < 4; rr++) {
            float acc = bias;
            #pragma unroll
            for (int j = 0; j < 7; j++) acc += w7[j] * yv[rr + j];
            vals[i][rr] = acc;
            lsum[rr] += acc; lsq[rr] += acc * acc;
        }
    }

    __shared__ float sw1[4][8], sw2[4][8];
    __shared__ float smean[4], srstd[4];
    #pragma unroll
    for (int rr = 0; rr < 4; rr++) {
        float a = lsum[rr], q = lsq[rr];
        #pragma unroll
        for (int d = 16; d > 0; d >>= 1) {
            a += __shfl_xor_sync(0xFFFFFFFFu, a, d);
            q += __shfl_xor_sync(0xFFFFFFFFu, q, d);
        }
        if (lane == 0) { sw1[rr][w] = a; sw2[rr][w] = q; }
    }
    __syncthreads();
    if (tid < 4) {
        float a = 0.f, q = 0.f;
        #pragma unroll
        for (int j = 0; j < 8; j++) { a += sw1[tid][j]; q += sw2[tid][j]; }
        float mean = a * (1.0f / C_);
        float var  = q * (1.0f / C_) - mean * mean;
        smean[tid] = mean;
        srstd[tid] = rsqrtf(var + 1e-5f);
    }
    __syncthreads();

    #pragma unroll
    for (int i = 0; i < 3; i++) {
        int c = tid + i * 256;
        float lw = lnw[c], lb = lnb[c];
        #pragma unroll
        for (int rr = 0; rr < 4; rr++) {
            float v = (vals[i][rr] - smean[rr]) * srstd[rr] * lw + lb;
            g_yn16[(size_t)(b*1024 + r0 + rr) * C_ + c] = __float2bfloat16(v);
        }
    }
}

// ======================= merged fp32 -> bf16 convert =======================
#define CV0 786432
#define CV1 (CV0 + 147456)
#define CV2 (CV1 + 294912)
#define CV3 (CV2 + 147456)
__global__ void __launch_bounds__(256) cvt_all_kernel(
    const float* __restrict__ x,  const float* __restrict__ qw,
    const float* __restrict__ kvw, const float* __restrict__ pw)
{
    int i = blockIdx.x * 256 + threadIdx.x;
    if (i >= CV3) return;
    const float* s; __nv_bfloat16* o; int off;
    if (i < CV0)      { s = x;   o = g_x16;   off = i; }
    else if (i < CV1) { s = qw;  o = g_qw16;  off = i - CV0; }
    else if (i < CV2) { s = kvw; o = g_kvw16; off = i - CV1; }
    else              { s = pw;  o = g_pw16;  off = i - CV2; }
    float4 v = ((const float4*)s)[off];
    __nv_bfloat162* O = (__nv_bfloat162*)o;
    O[2*off]   = __halves2bfloat162(__float2bfloat16(v.x), __float2bfloat16(v.y));
    O[2*off+1] = __halves2bfloat162(__float2bfloat16(v.z), __float2bfloat16(v.w));
}

// ======================= V transpose =======================
__global__ void __launch_bounds__(256) vtrans_kernel()
{
    int z  = blockIdx.x;
    int t0 = blockIdx.y * 32;
    int b = z / 12, h = z - b*12;
    __shared__ __nv_bfloat16 sh[64][33];
    int tid = threadIdx.x;
    #pragma unroll
    for (int i = 0; i < 8; i++) {
        int idx = tid + i*256;
        int tok = idx >> 6, d = idx & 63;
        size_t off = ((size_t)(b*1024 + t0 + tok)) * 1536 + 768 + h*64 + d;
        sh[d][tok] = g_kv16[off];
    }
    __syncthreads();
    #pragma unroll
    for (int i = 0; i < 8; i++) {
        int o = tid + i*256;
        int d = o >> 5, c = o & 31;
        size_t off = (size_t)z * 64 * 1024 + (size_t)d * 1024 + t0 + c;
        g_vt16[off] = sh[d][c];
    }
}

// ======================= HMMA GEMM (R10: 3-stage ring, 1 barrier/iter, x4 B-ldmatrix) =======================
template<int NT, int OUTM>
__global__ void __launch_bounds__(256) mma_gemm(
    const __nv_bfloat16* __restrict__ A, const __nv_bfloat16* __restrict__ B,
    float* __restrict__ Co, __nv_bfloat16* __restrict__ Cb,
    const float* __restrict__ bias, const float* __restrict__ res,
    int K, int lda, int ldb, int ldc, float alpha, int HH,
    long long aO, long long aI, long long bO, long long bI,
    long long cO, long long cI)
{
    constexpr int WM  = (NT == 128) ? 2 : 4;
    constexpr int WN  = 8 / WM;
    constexpr int WTM = 128 / WM;
    constexpr int WTN = NT / WN;
    constexpr int MT  = WTM / 16;
    constexpr int NTT = WTN / 8;
    constexpr int PITCH = 72;
    constexpr int ABYTES = 128 * PITCH * 2;
    constexpr int BBYTES = NT  * PITCH * 2;
    constexpr int STAGE  = ABYTES + BBYTES;

    extern __shared__ __align__(16) char dsm[];
    uint32_t smbase = smem_u32(dsm);

    int tid = threadIdx.x, wid = tid >> 5, lane = tid & 31;
    int wm = wid % WM, wn = wid / WM;

    int z = blockIdx.z, zo = z / HH, zi = z - zo * HH;
    A += zo*aO + zi*aI;
    B += zo*bO + zi*bI;
    long long coff = zo*cO + zi*cI;

    long long m0 = (long long)blockIdx.y * 128;
    long long n0 = (long long)blockIdx.x * NT;

    float acc[MT][NTT][4];
    #pragma unroll
    for (int i = 0; i < MT; i++)
        #pragma unroll
        for (int j = 0; j < NTT; j++)
            #pragma unroll
            for (int r = 0; r < 4; r++) acc[i][j][r] = 0.f;

    int nIter = K >> 6;

    uint32_t a_off = ((uint32_t)(wm*WTM + (lane & 15)) * PITCH + ((lane >> 4) << 3)) * 2;
    uint32_t b_off4 = ABYTES +
        ((uint32_t)(wn*WTN + (lane & 7) + ((lane >> 4) & 1) * 8) * PITCH
         + (((lane >> 3) & 1) << 3)) * 2;

    auto issue = [&](int t) {
        int k0 = t << 6, s = t % 3;
        uint32_t sa = smbase + s * STAGE;
        uint32_t sb = sa + ABYTES;
        #pragma unroll
        for (int i = 0; i < 4; i++) {
            int ch = tid + (i << 8);
            int r = ch >> 3, c = (ch & 7) << 3;
            cp16(sa + (uint32_t)(r*PITCH + c)*2, A + (m0 + r)*lda + k0 + c);
        }
        #pragma unroll
        for (int i = 0; i < NT/32; i++) {
            int ch = tid + (i << 8);
            int r = ch >> 3, c = (ch & 7) << 3;
            cp16(sb + (uint32_t)(r*PITCH + c)*2, B + (n0 + r)*ldb + k0 + c);
        }
        asm volatile("cp.async.commit_group;");
    };

    issue(0);
    if (nIter > 1) issue(1);
    for (int t = 0; t < nIter; t++) {
        if (t + 2 <= nIter) {
            asm volatile("cp.async.wait_group 1;");
        } else {
            asm volatile("cp.async.wait_group 0;");
        }
        __syncthreads();
        uint32_t stg = smbase + (uint32_t)(t % 3) * STAGE;
        uint32_t abase = stg + a_off;
        uint32_t bbase = stg + b_off4;

        #pragma unroll
        for (int ks = 0; ks < 4; ks++) {
            uint32_t kb = (uint32_t)ks << 5;
            uint32_t af[MT][4];
            #pragma unroll
            for (int mt = 0; mt < MT; mt++) {
                asm volatile("ldmatrix.sync.aligned.m8n8.x4.shared.b16 {%0,%1,%2,%3}, [%4];"
                    : "=r"(af[mt][0]), "=r"(af[mt][1]), "=r"(af[mt][2]), "=r"(af[mt][3])
                    : "r"(abase + (uint32_t)(mt*16*PITCH*2) + kb));
            }
            uint32_t bf[NTT][2];
            #pragma unroll
            for (int np = 0; np < NTT/2; np++) {
                asm volatile("ldmatrix.sync.aligned.m8n8.x4.shared.b16 {%0,%1,%2,%3}, [%4];"
                    : "=r"(bf[2*np][0]), "=r"(bf[2*np][1]),
                      "=r"(bf[2*np+1][0]), "=r"(bf[2*np+1][1])
                    : "r"(bbase + (uint32_t)(np*16*PITCH*2) + kb));
            }
            #pragma unroll
            for (int mt = 0; mt < MT; mt++)
                #pragma unroll
                for (int nt = 0; nt < NTT; nt++) {
                    asm volatile(
                        "mma.sync.aligned.m16n8k16.row.col.f32.bf16.bf16.f32 "
                        "{%0,%1,%2,%3}, {%4,%5,%6,%7}, {%8,%9}, {%0,%1,%2,%3};"
                        : "+f"(acc[mt][nt][0]), "+f"(acc[mt][nt][1]),
                          "+f"(acc[mt][nt][2]), "+f"(acc[mt][nt][3])
                        : "r"(af[mt][0]), "r"(af[mt][1]), "r"(af[mt][2]), "r"(af[mt][3]),
                          "r"(bf[nt][0]), "r"(bf[nt][1]));
                }
        }
        if (t + 2 < nIter) issue(t + 2);
    }

    int gg = lane >> 2, qq = lane & 3;
    #pragma unroll
    for (int mt = 0; mt < MT; mt++) {
        long long gm = m0 + wm*WTM + mt*16 + gg;
        #pragma unroll
        for (int nt = 0; nt < NTT; nt++) {
            long long gn = n0 + wn*WTN + nt*8 + 2*qq;
            float v0 = acc[mt][nt][0] * alpha;
            float v1 = acc[mt][nt][1] * alpha;
            float v2 = acc[mt][nt][2] * alpha;
            float v3 = acc[mt][nt][3] * alpha;
            long long gi0 = coff + gm * (long long)ldc + gn;
            long long gi1 = gi0 + 8LL * ldc;
            if (OUTM == 0) {
                *(float2*)&Co[gi0] = make_float2(v0, v1);
                *(float2*)&Co[gi1] = make_float2(v2, v3);
            } else if (OUTM == 1) {
                float b0 = bias[gn], b1 = bias[gn + 1];
                float2 r0 = *(const float2*)&res[gi0];
                float2 r1 = *(const float2*)&res[gi1];
                *(float2*)&Co[gi0] = make_float2(v0 + b0 + r0.x, v1 + b1 + r0.y);
                *(float2*)&Co[gi1] = make_float2(v2 + b0 + r1.x, v3 + b1 + r1.y);
            } else {
                *(__nv_bfloat162*)&Cb[gi0] =
                    __halves2bfloat162(__float2bfloat16(v0), __float2bfloat16(v1));
                *(__nv_bfloat162*)&Cb[gi1] =
                    __halves2bfloat162(__float2bfloat16(v2), __float2bfloat16(v3));
            }
        }
    }
}

// ======================= warp-per-row dual top-k select -> W (bf16) =======================
__global__ void __launch_bounds__(256) select_kernel(
    const float* __restrict__ Sbase, __nv_bfloat16* __restrict__ Wbase,
    const int* __restrict__ pk1, const int* __restrict__ pk2)
{
    __shared__ unsigned hist[8][512];

    int tid = threadIdx.x, lane = tid & 31, wid = tid >> 5;
    long long row = (long long)blockIdx.x * 8 + wid;
    const float* Srow = Sbase + row * 1024;

    unsigned u[32];
    unsigned umax = 0u;
    #pragma unroll
    for (int j = 0; j < 8; j++) {
        float4 f = *(const float4*)(Srow + j*128 + lane*4);
        float vv[4] = {f.x, f.y, f.z, f.w};
        #pragma unroll
        for (int e = 0; e < 4; e++) {
            unsigned b = __float_as_uint(vv[e]);
            unsigned k = (b & 0x80000000u) ? ~b : (b | 0x80000000u);
            u[j*4 + e] = k;
            umax = (k > umax) ? k : umax;
        }
    }
    #pragma unroll
    for (int d = 16; d > 0; d >>= 1) {
        unsigned o = __shfl_xor_sync(0xFFFFFFFFu, umax, d);
        umax = (o > umax) ? o : umax;
    }
    float m = (umax & 0x80000000u) ? __uint_as_float(umax & 0x7FFFFFFFu)
                                   : __uint_as_float(~umax);

    int k1 = *pk1, k2 = *pk2;
    unsigned* h0 = hist[wid];
    unsigned* h1 = hist[wid] + 256;

    auto scan1 = [&](const unsigned* h, unsigned pfx, int kk, int sh,
                     unsigned& pout, int& kout) {
        unsigned h8[8];
        #pragma unroll
        for (int i = 0; i < 8; i++) h8[i] = h[lane*8 + i];
        unsigned tot = 0;
        #pragma unroll
        for (int i = 0; i < 8; i++) tot += h8[i];
        unsigned s = tot;
        #pragma unroll
        for (int d = 1; d < 32; d <<= 1) {
            unsigned t = __shfl_down_sync(0xFFFFFFFFu, s, d);
            if (lane + d < 32) s += t;
        }
        unsigned run = s - tot;
        unsigned myp = 0u; int myk = 0; bool found = false;
        #pragma unroll
        for (int i = 7; i >= 0; i--) {
            unsigned cn = run;
            run += h8[i];
            if (!found && run >= (unsigned)kk && cn < (unsigned)kk) {
                found = true;
                myp = pfx | ((unsigned)(lane*8 + i) << sh);
                myk = kk - (int)cn;
            }
        }
        unsigned ball = __ballot_sync(0xFFFFFFFFu, found);
        int src = __ffs(ball) - 1;
        pout = __shfl_sync(0xFFFFFFFFu, myp, src);
        kout = __shfl_sync(0xFFFFFFFFu, myk, src);
    };

    // level 3
    #pragma unroll
    for (int i = 0; i < 8; i++) h0[lane*8 + i] = 0u;
    __syncwarp();
    #pragma unroll
    for (int j = 0; j < 32; j++) atomicAdd(&h0[u[j] >> 24], 1u);
    __syncwarp();
    unsigned p1, p2; int kk1, kk2;
    scan1(h0, 0u, k1, 24, p1, kk1);
    scan1(h0, 0u, k2, 24, p2, kk2);

    // levels 2..0
    #pragma unroll
    for (int lev = 2; lev >= 0; lev--) {
        int sh = lev * 8;
        unsigned himask = 0xFFFFFFFFu << (sh + 8);
        bool same = (p1 == p2);
        __syncwarp();
        #pragma unroll
        for (int i = 0; i < 16; i++) hist[wid][lane*16 + i] = 0u;
        __syncwarp();
        #pragma unroll
        for (int j = 0; j < 32; j++) {
            unsigned uu = u[j];
            if (((uu ^ p1) & himask) == 0u) atomicAdd(&h0[(uu >> sh) & 255u], 1u);
            if (!same && ((uu ^ p2) & himask) == 0u) atomicAdd(&h1[(uu >> sh) & 255u], 1u);
        }
        __syncwarp();
        unsigned p1o = p1, p2o = p2;
        scan1(h0, p1o, kk1, sh, p1, kk1);
        scan1(same ? h0 : h1, p2o, kk2, sh, p2, kk2);
    }

    // masked Z sums
    float ev[32];
    float z1 = 0.f, z2 = 0.f;
    #pragma unroll
    for (int j = 0; j < 32; j++) {
        unsigned uu = u[j];
        float v = (uu & 0x80000000u) ? __uint_as_float(uu & 0x7FFFFFFFu)
                                     : __uint_as_float(~uu);
        float e = __expf(v - m);
        ev[j] = e;
        if (uu >= p1) z1 += e;
        if (uu >= p2) z2 += e;
    }
    #pragma unroll
    for (int d = 16; d > 0; d >>= 1) {
        z1 += __shfl_xor_sync(0xFFFFFFFFu, z1, d);
        z2 += __shfl_xor_sync(0xFFFFFFFFu, z2, d);
    }
    float c1 = 0.6f / z1;
    float c2 = 0.4f / z2;

    __nv_bfloat16* Wrow = Wbase + row * 1024;
    #pragma unroll
    for (int j = 0; j < 8; j++) {
        __nv_bfloat16 o4[4];
        #pragma unroll
        for (int e = 0; e < 4; e++) {
            unsigned uu = u[j*4 + e];
            float x = ev[j*4 + e];
            float w = x * ((uu >= p1) ? c1 : 0.f) + x * ((uu >= p2) ? c2 : 0.f);
            o4[e] = __float2bfloat16(w);
        }
        *(uint2*)&Wrow[j*128 + lane*4] = *(uint2*)o4;
    }
}

// ======================= launch (multi-stream fork-join DAG) =======================
extern "C" void kernel_launch(void* const* d_in, const int* in_sizes, int n_in,
                              void* d_out, int out_size)
{
    const float* x   = (const float*)d_in[0];
    const float* y   = (const float*)d_in[1];
    const float* c1w = (const float*)d_in[2];
    const float* c1b = (const float*)d_in[3];
    const float* c2w = (const float*)d_in[4];
    const float* c2b = (const float*)d_in[5];
    const float* c3w = (const float*)d_in[6];
    const float* c3b = (const float*)d_in[7];
    const float* lnw = (const float*)d_in[8];
    const float* lnb = (const float*)d_in[9];
    const float* qw  = (const float*)d_in[10];
    const float* kvw = (const float*)d_in[11];
    const float* pw  = (const float*)d_in[12];
    const float* pb  = (const float*)d_in[13];
    const int*   pk1 = (const int*)d_in[14];
    const int*   pk2 = (const int*)d_in[15];
    float* out = (float*)d_out;

    #define SYM(p, g) void* p; cudaGetSymbolAddress(&p, g)
    SYM(S, g_S);
    SYM(x16, g_x16);   SYM(yn16, g_yn16);
    SYM(q16, g_q16);   SYM(kv16, g_kv16);
    SYM(vt16, g_vt16); SYM(W, g_W);
    SYM(at16, g_at16);
    SYM(qw16, g_qw16); SYM(kvw16, g_kvw16); SYM(pw16, g_pw16);
    #undef SYM
    float* Sb[2] = { (float*)S, (float*)S + (size_t)12*1024*1024 };

    // one-time host handles (no device memory)
    static cudaStream_t s2 = nullptr;
    static cudaEvent_t evFork, evCvt, evQ, evKv, evVt, evSc[4], evSel[4];
    if (!s2) {
        cudaStreamCreateWithFlags(&s2, cudaStreamNonBlocking);
        cudaEventCreateWithFlags(&evFork, cudaEventDisableTiming);
        cudaEventCreateWithFlags(&evCvt,  cudaEventDisableTiming);
        cudaEventCreateWithFlags(&evQ,    cudaEventDisableTiming);
        cudaEventCreateWithFlags(&evKv,   cudaEventDisableTiming);
        cudaEventCreateWithFlags(&evVt,   cudaEventDisableTiming);
        for (int g = 0; g < 4; g++) {
            cudaEventCreateWithFlags(&evSc[g],  cudaEventDisableTiming);
            cudaEventCreateWithFlags(&evSel[g], cudaEventDisableTiming);
        }
    }

    const int SM128 = 3 * (128 + 128) * 72 * 2;   // 110592
    const int SM64  = 3 * (128 + 64)  * 72 * 2;   // 82944
    cudaFuncSetAttribute(mma_gemm<128,0>, cudaFuncAttributeMaxDynamicSharedMemorySize, SM128);
    cudaFuncSetAttribute(mma_gemm<128,1>, cudaFuncAttributeMaxDynamicSharedMemorySize, SM128);
    cudaFuncSetAttribute(mma_gemm<128,2>, cudaFuncAttributeMaxDynamicSharedMemorySize, SM128);
    cudaFuncSetAttribute(mma_gemm<64,2>,  cudaFuncAttributeMaxDynamicSharedMemorySize, SM64);

    // ---- fork side stream from origin ----
    cudaEventRecord(evFork, 0);
    cudaStreamWaitEvent(s2, evFork, 0);

    // s0: conv + LN
    conv_ln_kernel<<<1024, 256, 0, 0>>>(y, c1w, c1b, c2w, c2b, c3w, c3b, lnw, lnb);

    // s2: conversions, then q GEMM (needs only cvt outputs)
    cvt_all_kernel<<<(CV3 + 255)/256, 256, 0, s2>>>(x, qw, kvw, pw);
    cudaEventRecord(evCvt, s2);
    mma_gemm<128,2><<<dim3(6,32,1), 256, SM128, s2>>>(
        (const __nv_bfloat16*)x16, (const __nv_bfloat16*)qw16,
        nullptr, (__nv_bfloat16*)q16, nullptr, nullptr,
        768, 768, 768, 768, 1.0f, 1, 0,0,0,0,0,0);
    cudaEventRecord(evQ, s2);

    // s0: kv GEMM (needs conv_ln in-order + cvt's kvw16)
    cudaStreamWaitEvent(0, evCvt, 0);
    mma_gemm<128,2><<<dim3(12,32,1), 256, SM128, 0>>>(
        (const __nv_bfloat16*)yn16, (const __nv_bfloat16*)kvw16,
        nullptr, (__nv_bfloat16*)kv16, nullptr, nullptr,
        768, 768, 768, 1536, 1.0f, 1, 0,0,0,0,0,0);
    cudaEventRecord(evKv, 0);

    // s2: V transpose (needs kv), overlaps with score GEMMs on s0
    cudaStreamWaitEvent(s2, evKv, 0);
    vtrans_kernel<<<dim3(48,32), 256, 0, s2>>>();
    cudaEventRecord(evVt, s2);

    // s0: score groups; s2: selects, pipelined with double-buffered S
    cudaStreamWaitEvent(0, evQ, 0);
    for (int g = 0; g < 4; g++) {
        const __nv_bfloat16* qg  = (const __nv_bfloat16*)q16  + (size_t)g * 1024 * 768;
        const __nv_bfloat16* kvg = (const __nv_bfloat16*)kv16 + (size_t)g * 1024 * 1536;
        __nv_bfloat16* Wg = (__nv_bfloat16*)W + (size_t)g * 12 * 1024 * 1024;
        float* Sg = Sb[g & 1];

        if (g >= 2) cudaStreamWaitEvent(0, evSel[g - 2], 0);   // buffer reuse hazard
        mma_gemm<128,0><<<dim3(8,8,12), 256, SM128, 0>>>(
            qg, kvg, Sg, nullptr, nullptr, nullptr,
            64, 768, 1536, 1024, 0.125f, 12,
            0, 64, 0, 64, 0, (long long)1024*1024);
        cudaEventRecord(evSc[g], 0);

        cudaStreamWaitEvent(s2, evSc[g], 0);
        select_kernel<<<12*1024/8, 256, 0, s2>>>((const float*)Sg, Wg, pk1, pk2);
        cudaEventRecord(evSel[g], s2);
    }

    // s0: join — WV needs all W (selects) and vt16
    cudaStreamWaitEvent(0, evVt, 0);
    cudaStreamWaitEvent(0, evSel[3], 0);
    mma_gemm<64,2><<<dim3(1,8,48), 256, SM64, 0>>>(
        (const __nv_bfloat16*)W, (const __nv_bfloat16*)vt16,
        nullptr, (__nv_bfloat16*)at16, nullptr, nullptr,
        1024, 1024, 1024, 768, 1.0f, 12,
        (long long)12*1024*1024, (long long)1024*1024,
        (long long)12*64*1024,   (long long)64*1024,
        (long long)1024*768, 64);

    // s0: out = attn @ proj_w^T + proj_b + x
    mma_gemm<128,1><<<dim3(6,32,1), 256, SM128, 0>>>(
        (const __nv_bfloat16*)at16, (const __nv_bfloat16*)pw16,
        out, nullptr, pb, x,
        768, 768, 768, 768, 1.0f, 1, 0,0,0,0,0,0);
}